// round 3
// baseline (speedup 1.0000x reference)
#include <cuda_runtime.h>
#include <math.h>

// Problem constants
#define BB   2
#define SS   2048
#define HIDD 2048
#define NH   32
#define NKV  8
#define HD   64
#define NREP 4

// Scratch (device globals: allocation-free rule)
__device__ float g_q[BB * SS * NH * HD];     // [B,S,NH*HD]
__device__ float g_k[BB * SS * NKV * HD];    // [B,S,NKV*HD]
__device__ float g_v[BB * SS * NKV * HD];    // [B,S,NKV*HD]
__device__ float g_attn[BB * SS * NH * HD];  // [B,S,NH*HD]

// ---------------------------------------------------------------------------
// NT SGEMM: C[M,N] = A[M,K] * B[N,K]^T   (both row-major, K contiguous)
// BM=BN=128, BK=16, 256 threads, 8x8 per-thread micro-tile.
// M % 128 == 0, N % 128 == 0, K % 16 == 0 guaranteed by problem shapes.
// ---------------------------------------------------------------------------
__global__ void __launch_bounds__(256) sgemm_nt(const float* __restrict__ A,
                                                const float* __restrict__ Bw,
                                                float* __restrict__ C,
                                                int M, int N, int K) {
    const int BM = 128, BN = 128, BK = 16;
    __shared__ float As[BK][BM];
    __shared__ float Bs[BK][BN];

    int tid = threadIdx.x;
    int m0 = blockIdx.y * BM;
    int n0 = blockIdx.x * BN;
    int tx = tid % 16;   // n micro index
    int ty = tid / 16;   // m micro index

    int lr = tid / 4;          // row within tile half (0..63)
    int lc = (tid % 4) * 4;    // k col (0,4,8,12)

    const float* Aptr = A + (long)m0 * K;
    const float* Bptr = Bw + (long)n0 * K;

    float acc[8][8];
#pragma unroll
    for (int i = 0; i < 8; i++)
#pragma unroll
        for (int j = 0; j < 8; j++) acc[i][j] = 0.f;

    for (int k0 = 0; k0 < K; k0 += BK) {
        float4 a0 = *(const float4*)(Aptr + (long)(lr)      * K + k0 + lc);
        float4 a1 = *(const float4*)(Aptr + (long)(lr + 64) * K + k0 + lc);
        float4 b0 = *(const float4*)(Bptr + (long)(lr)      * K + k0 + lc);
        float4 b1 = *(const float4*)(Bptr + (long)(lr + 64) * K + k0 + lc);

        __syncthreads();   // previous tile fully consumed

        As[lc + 0][lr] = a0.x; As[lc + 1][lr] = a0.y;
        As[lc + 2][lr] = a0.z; As[lc + 3][lr] = a0.w;
        As[lc + 0][lr + 64] = a1.x; As[lc + 1][lr + 64] = a1.y;
        As[lc + 2][lr + 64] = a1.z; As[lc + 3][lr + 64] = a1.w;
        Bs[lc + 0][lr] = b0.x; Bs[lc + 1][lr] = b0.y;
        Bs[lc + 2][lr] = b0.z; Bs[lc + 3][lr] = b0.w;
        Bs[lc + 0][lr + 64] = b1.x; Bs[lc + 1][lr + 64] = b1.y;
        Bs[lc + 2][lr + 64] = b1.z; Bs[lc + 3][lr + 64] = b1.w;

        __syncthreads();

#pragma unroll
        for (int kk = 0; kk < BK; kk++) {
            float ra[8], rb[8];
            *(float4*)&ra[0] = *(const float4*)&As[kk][ty * 8];
            *(float4*)&ra[4] = *(const float4*)&As[kk][ty * 8 + 4];
            *(float4*)&rb[0] = *(const float4*)&Bs[kk][tx * 8];
            *(float4*)&rb[4] = *(const float4*)&Bs[kk][tx * 8 + 4];
#pragma unroll
            for (int i = 0; i < 8; i++)
#pragma unroll
                for (int j = 0; j < 8; j++) acc[i][j] += ra[i] * rb[j];
        }
    }

#pragma unroll
    for (int i = 0; i < 8; i++) {
        float* crow = C + (long)(m0 + ty * 8 + i) * N + n0 + tx * 8;
        *(float4*)(crow + 0) = make_float4(acc[i][0], acc[i][1], acc[i][2], acc[i][3]);
        *(float4*)(crow + 4) = make_float4(acc[i][4], acc[i][5], acc[i][6], acc[i][7]);
    }
}

// ---------------------------------------------------------------------------
// RoPE: in-place on [B,S,H,HD] with rotate_half pairing (i, i+32)
// ---------------------------------------------------------------------------
__global__ void rope_kernel(float* __restrict__ x,
                            const float* __restrict__ cosb,
                            const float* __restrict__ sinb,
                            int nheads, int total_pairs) {
    int idx = blockIdx.x * blockDim.x + threadIdx.x;
    if (idx >= total_pairs) return;
    int i = idx & 31;
    int h = (idx >> 5) % nheads;
    int s = (idx / (32 * nheads)) % SS;
    int b = idx / (32 * nheads * SS);
    long base = ((long)(b * SS + s) * nheads + h) * HD;
    float x1 = x[base + i];
    float x2 = x[base + i + 32];
    float c1 = cosb[s * HD + i];
    float s1 = sinb[s * HD + i];
    float c2 = cosb[s * HD + i + 32];
    float s2 = sinb[s * HD + i + 32];
    x[base + i]      = x1 * c1 - x2 * s1;
    x[base + i + 32] = x2 * c2 + x1 * s2;
}

// ---------------------------------------------------------------------------
// Flash attention (GQA): one q row per thread, 128 rows per block.
// grid = (S/128, NH, B); K/V tiles of 32 rows staged in SMEM.
// ---------------------------------------------------------------------------
__global__ void __launch_bounds__(128) flash_attn(const float* __restrict__ Q,
                                                  const float* __restrict__ Kg,
                                                  const float* __restrict__ Vg,
                                                  float* __restrict__ O) {
    const int TK = 32;
    __shared__ float Ks[TK * HD];
    __shared__ float Vs[TK * HD];

    int tid = threadIdx.x;
    int h   = blockIdx.y;
    int b   = blockIdx.z;
    int row = blockIdx.x * 128 + tid;
    int kvh = h >> 2;  // NREP = 4

    const float scale = 0.125f;  // 1/sqrt(64)

    // q row into registers
    float qreg[HD];
    const float* qp = Q + ((long)(b * SS + row) * (NH * HD)) + h * HD;
#pragma unroll
    for (int d = 0; d < HD; d += 4) {
        float4 t = *(const float4*)(qp + d);
        qreg[d] = t.x; qreg[d + 1] = t.y; qreg[d + 2] = t.z; qreg[d + 3] = t.w;
    }

    float m = -INFINITY, l = 0.f;
    float acc[HD];
#pragma unroll
    for (int d = 0; d < HD; d++) acc[d] = 0.f;

    const float* kbase = Kg + (long)b * SS * (NKV * HD) + kvh * HD;
    const float* vbase = Vg + (long)b * SS * (NKV * HD) + kvh * HD;

    for (int j0 = 0; j0 < SS; j0 += TK) {
        // cooperative load K/V tile: TK*HD = 2048 floats, 128 threads, float4
#pragma unroll
        for (int it = 0; it < 4; it++) {
            int fidx = (tid + it * 128) * 4;     // flat float index
            int jr = fidx / HD;
            int dc = fidx % HD;
            const float* ksrc = kbase + (long)(j0 + jr) * (NKV * HD) + dc;
            const float* vsrc = vbase + (long)(j0 + jr) * (NKV * HD) + dc;
            *(float4*)&Ks[fidx] = *(const float4*)ksrc;
            *(float4*)&Vs[fidx] = *(const float4*)vsrc;
        }
        __syncthreads();

        // scores for this tile
        float sreg[TK];
#pragma unroll 4
        for (int j = 0; j < TK; j++) {
            float dot = 0.f;
#pragma unroll
            for (int d = 0; d < HD; d += 4) {
                float4 kv = *(const float4*)&Ks[j * HD + d];
                dot += qreg[d] * kv.x + qreg[d + 1] * kv.y +
                       qreg[d + 2] * kv.z + qreg[d + 3] * kv.w;
            }
            sreg[j] = dot * scale;
        }

        // online softmax update
        float mt = sreg[0];
#pragma unroll
        for (int j = 1; j < TK; j++) mt = fmaxf(mt, sreg[j]);
        float m_new = fmaxf(m, mt);
        float corr = __expf(m - m_new);
        float psum = 0.f;
#pragma unroll
        for (int j = 0; j < TK; j++) {
            sreg[j] = __expf(sreg[j] - m_new);
            psum += sreg[j];
        }
        l = l * corr + psum;
#pragma unroll
        for (int d = 0; d < HD; d++) acc[d] *= corr;
#pragma unroll 2
        for (int j = 0; j < TK; j++) {
            float p = sreg[j];
#pragma unroll
            for (int d = 0; d < HD; d += 4) {
                float4 vv = *(const float4*)&Vs[j * HD + d];
                acc[d]     += p * vv.x;
                acc[d + 1] += p * vv.y;
                acc[d + 2] += p * vv.z;
                acc[d + 3] += p * vv.w;
            }
        }
        m = m_new;
        __syncthreads();
    }

    float inv_l = 1.f / l;
    float* op = O + ((long)(b * SS + row) * (NH * HD)) + h * HD;
#pragma unroll
    for (int d = 0; d < HD; d += 4) {
        *(float4*)(op + d) = make_float4(acc[d] * inv_l, acc[d + 1] * inv_l,
                                         acc[d + 2] * inv_l, acc[d + 3] * inv_l);
    }
}

// ---------------------------------------------------------------------------
// Launch
// ---------------------------------------------------------------------------
extern "C" void kernel_launch(void* const* d_in, const int* in_sizes, int n_in,
                              void* d_out, int out_size) {
    const float* x    = (const float*)d_in[0];  // hidden_states [B,S,HID]
    const float* cosb = (const float*)d_in[1];  // [S,HD]
    const float* sinb = (const float*)d_in[2];  // [S,HD]
    const float* wq   = (const float*)d_in[3];  // [NH*HD, HID]
    const float* wk   = (const float*)d_in[4];  // [NKV*HD, HID]
    const float* wv   = (const float*)d_in[5];  // [NKV*HD, HID]
    const float* wo   = (const float*)d_in[6];  // [HID, NH*HD]
    float* out = (float*)d_out;

    void *pq, *pk, *pv, *pa;
    cudaGetSymbolAddress(&pq, g_q);
    cudaGetSymbolAddress(&pk, g_k);
    cudaGetSymbolAddress(&pv, g_v);
    cudaGetSymbolAddress(&pa, g_attn);
    float* Q = (float*)pq;
    float* K = (float*)pk;
    float* V = (float*)pv;
    float* A = (float*)pa;

    const int M = BB * SS;         // 4096
    const int HK = HIDD;           // 2048

    // Projections
    sgemm_nt<<<dim3(NH * HD / 128, M / 128), 256>>>(x, wq, Q, M, NH * HD, HK);
    sgemm_nt<<<dim3(NKV * HD / 128, M / 128), 256>>>(x, wk, K, M, NKV * HD, HK);
    sgemm_nt<<<dim3(NKV * HD / 128, M / 128), 256>>>(x, wv, V, M, NKV * HD, HK);

    // RoPE
    int qpairs = BB * SS * NH * 32;
    int kpairs = BB * SS * NKV * 32;
    rope_kernel<<<(qpairs + 255) / 256, 256>>>(Q, cosb, sinb, NH, qpairs);
    rope_kernel<<<(kpairs + 255) / 256, 256>>>(K, cosb, sinb, NKV, kpairs);

    // Attention
    flash_attn<<<dim3(SS / 128, NH, BB), 128>>>(Q, K, V, A);

    // Output projection
    sgemm_nt<<<dim3(HIDD / 128, M / 128), 256>>>(A, wo, out, M, HIDD, HK);
}

// round 7
// speedup vs baseline: 1.3893x; 1.3893x over previous
#include <cuda_runtime.h>
#include <cuda_bf16.h>
#include <math.h>
#include <stdint.h>

// Problem constants
#define BB   2
#define SS   2048
#define HIDD 2048
#define NH   32
#define NKV  8
#define HD   64
#define NREP 4

// ---------------------------------------------------------------------------
// Device-global scratch (allocation-free rule)
// ---------------------------------------------------------------------------
__device__ float g_q[BB * SS * NH * HD];     // [B,S,NH*HD]
__device__ float g_k[BB * SS * NKV * HD];    // [B,S,NKV*HD]
__device__ float g_v[BB * SS * NKV * HD];    // [B,S,NKV*HD]
__device__ float g_attn[BB * SS * NH * HD];  // [B,S,NH*HD]

// split-bf16 operands
__device__ __nv_bfloat16 g_x_hi[BB * SS * HIDD];
__device__ __nv_bfloat16 g_x_lo[BB * SS * HIDD];
__device__ __nv_bfloat16 g_wq_hi[NH * HD * HIDD];
__device__ __nv_bfloat16 g_wq_lo[NH * HD * HIDD];
__device__ __nv_bfloat16 g_wk_hi[NKV * HD * HIDD];
__device__ __nv_bfloat16 g_wk_lo[NKV * HD * HIDD];
__device__ __nv_bfloat16 g_wv_hi[NKV * HD * HIDD];
__device__ __nv_bfloat16 g_wv_lo[NKV * HD * HIDD];
__device__ __nv_bfloat16 g_wo_hi[HIDD * NH * HD];
__device__ __nv_bfloat16 g_wo_lo[HIDD * NH * HD];
__device__ __nv_bfloat16 g_a_hi[BB * SS * NH * HD];
__device__ __nv_bfloat16 g_a_lo[BB * SS * NH * HD];

// ---------------------------------------------------------------------------
// Helpers
// ---------------------------------------------------------------------------
__device__ __forceinline__ uint32_t smem_u32(const void* p) {
    uint32_t a;
    asm("{ .reg .u64 t; cvta.to.shared.u64 t, %1; cvt.u32.u64 %0, t; }"
        : "=r"(a) : "l"(p));
    return a;
}

// swizzled byte offset inside a 128x32-bf16 tile (row stride 64B, 4x16B chunks)
__device__ __forceinline__ uint32_t sw_off(int row, int ch) {
    return (uint32_t)(row * 64 + ((ch ^ ((row >> 1) & 3)) << 4));
}

__device__ __forceinline__ void ldsm_x4(uint32_t addr, uint32_t& r0, uint32_t& r1,
                                        uint32_t& r2, uint32_t& r3) {
    asm volatile("ldmatrix.sync.aligned.m8n8.x4.shared.b16 {%0,%1,%2,%3}, [%4];"
                 : "=r"(r0), "=r"(r1), "=r"(r2), "=r"(r3) : "r"(addr));
}

__device__ __forceinline__ void mma_bf16(float* c, const uint32_t* a, const uint32_t* b) {
    asm volatile(
        "mma.sync.aligned.m16n8k16.row.col.f32.bf16.bf16.f32 "
        "{%0,%1,%2,%3}, {%4,%5,%6,%7}, {%8,%9}, {%0,%1,%2,%3};"
        : "+f"(c[0]), "+f"(c[1]), "+f"(c[2]), "+f"(c[3])
        : "r"(a[0]), "r"(a[1]), "r"(a[2]), "r"(a[3]), "r"(b[0]), "r"(b[1]));
}

// ---------------------------------------------------------------------------
// Split fp32 -> (hi, lo) bf16
// ---------------------------------------------------------------------------
__global__ void cvt_split(const float* __restrict__ in,
                          __nv_bfloat16* __restrict__ hi,
                          __nv_bfloat16* __restrict__ lo, int n) {
    int i = (blockIdx.x * blockDim.x + threadIdx.x) * 4;
    if (i >= n) return;
    float4 f = *(const float4*)(in + i);
    __nv_bfloat16 h0 = __float2bfloat16(f.x);
    __nv_bfloat16 h1 = __float2bfloat16(f.y);
    __nv_bfloat16 h2 = __float2bfloat16(f.z);
    __nv_bfloat16 h3 = __float2bfloat16(f.w);
    __nv_bfloat16 l0 = __float2bfloat16(f.x - __bfloat162float(h0));
    __nv_bfloat16 l1 = __float2bfloat16(f.y - __bfloat162float(h1));
    __nv_bfloat16 l2 = __float2bfloat16(f.z - __bfloat162float(h2));
    __nv_bfloat16 l3 = __float2bfloat16(f.w - __bfloat162float(h3));
    __nv_bfloat162* hp = (__nv_bfloat162*)(hi + i);
    __nv_bfloat162* lp = (__nv_bfloat162*)(lo + i);
    hp[0] = __nv_bfloat162(h0, h1);
    hp[1] = __nv_bfloat162(h2, h3);
    lp[0] = __nv_bfloat162(l0, l1);
    lp[1] = __nv_bfloat162(l2, l3);
}

// ---------------------------------------------------------------------------
// Split-bf16 NT GEMM on HMMA (mma.sync m16n8k16):
//   C[M,N] = A[M,K] * B[N,K]^T, fp32-equivalent via hi*hi + hi*lo + lo*hi.
// 128x128 CTA tile, BK=32, 8 warps (4 M x 2 N), warp tile 32x64.
// ---------------------------------------------------------------------------
__global__ void __launch_bounds__(256, 1)
gemm_tc(const __nv_bfloat16* __restrict__ Ahi, const __nv_bfloat16* __restrict__ Alo,
        const __nv_bfloat16* __restrict__ Bhi, const __nv_bfloat16* __restrict__ Blo,
        float* __restrict__ C, int M, int N, int K) {
    __shared__ __align__(16) char sAh[8192];
    __shared__ __align__(16) char sAl[8192];
    __shared__ __align__(16) char sBh[8192];
    __shared__ __align__(16) char sBl[8192];

    const int tid = threadIdx.x;
    const int wid = tid >> 5;
    const int lid = tid & 31;
    const int m0 = blockIdx.y * 128;
    const int n0 = blockIdx.x * 128;
    const int m0w = (wid >> 1) * 32;
    const int n0w = (wid & 1) * 64;

    const long ldb = (long)K * 2;  // row stride in bytes
    const char* aH = (const char*)(Ahi + (long)m0 * K);
    const char* aL = (const char*)(Alo + (long)m0 * K);
    const char* bH = (const char*)(Bhi + (long)n0 * K);
    const char* bL = (const char*)(Blo + (long)n0 * K);

    const uint32_t uAh = smem_u32(sAh), uAl = smem_u32(sAl);
    const uint32_t uBh = smem_u32(sBh), uBl = smem_u32(sBl);

    // per-thread store slots (2 chunks of 16B per tile)
    const int r0 = tid >> 2, c0 = tid & 3;          // rows 0..63
    const int r1 = (tid + 256) >> 2, c1 = tid & 3;  // rows 64..127
    const uint32_t so0 = sw_off(r0, c0), so1 = sw_off(r1, c1);
    const long go0 = (long)r0 * ldb + c0 * 16;
    const long go1 = (long)r1 * ldb + c1 * 16;

    float acc[2][8][4];
#pragma unroll
    for (int i = 0; i < 2; i++)
#pragma unroll
        for (int j = 0; j < 8; j++)
#pragma unroll
            for (int v = 0; v < 4; v++) acc[i][j][v] = 0.f;

    // prefetch iter 0
    uint4 pf[8];
    {
        const long kb = 0;
        pf[0] = *(const uint4*)(aH + go0 + kb); pf[1] = *(const uint4*)(aH + go1 + kb);
        pf[2] = *(const uint4*)(aL + go0 + kb); pf[3] = *(const uint4*)(aL + go1 + kb);
        pf[4] = *(const uint4*)(bH + go0 + kb); pf[5] = *(const uint4*)(bH + go1 + kb);
        pf[6] = *(const uint4*)(bL + go0 + kb); pf[7] = *(const uint4*)(bL + go1 + kb);
    }

    const int niter = K >> 5;
    for (int it = 0; it < niter; it++) {
        __syncthreads();  // previous tile fully consumed
        *(uint4*)(sAh + so0) = pf[0]; *(uint4*)(sAh + so1) = pf[1];
        *(uint4*)(sAl + so0) = pf[2]; *(uint4*)(sAl + so1) = pf[3];
        *(uint4*)(sBh + so0) = pf[4]; *(uint4*)(sBh + so1) = pf[5];
        *(uint4*)(sBl + so0) = pf[6]; *(uint4*)(sBl + so1) = pf[7];
        __syncthreads();

        // prefetch next tile (wraps to 0 on last iter; values discarded)
        {
            const long kb = (it + 1 < niter) ? (long)(it + 1) * 64 : 0;
            pf[0] = *(const uint4*)(aH + go0 + kb); pf[1] = *(const uint4*)(aH + go1 + kb);
            pf[2] = *(const uint4*)(aL + go0 + kb); pf[3] = *(const uint4*)(aL + go1 + kb);
            pf[4] = *(const uint4*)(bH + go0 + kb); pf[5] = *(const uint4*)(bH + go1 + kb);
            pf[6] = *(const uint4*)(bL + go0 + kb); pf[7] = *(const uint4*)(bL + go1 + kb);
        }

#pragma unroll
        for (int ks = 0; ks < 2; ks++) {
            uint32_t ah[2][4], al[2][4], bh[8][2], bl[8][2];
            // A fragments: lanes 0-15 -> rows, lanes 16-31 -> k-chunk +1
            const int arow = m0w + (lid & 15);
            const int ach = ks * 2 + (lid >> 4);
#pragma unroll
            for (int mi = 0; mi < 2; mi++) {
                uint32_t off = sw_off(arow + mi * 16, ach);
                ldsm_x4(uAh + off, ah[mi][0], ah[mi][1], ah[mi][2], ah[mi][3]);
                ldsm_x4(uAl + off, al[mi][0], al[mi][1], al[mi][2], al[mi][3]);
            }
            // B fragments: groups of 16 n-rows
            const int brow = n0w + (lid & 15);
            const int bch = ks * 2 + (lid >> 4);
#pragma unroll
            for (int g = 0; g < 4; g++) {
                uint32_t off = sw_off(brow + g * 16, bch);
                uint32_t t0, t1, t2, t3;
                ldsm_x4(uBh + off, t0, t1, t2, t3);
                bh[2 * g][0] = t0; bh[2 * g][1] = t2;
                bh[2 * g + 1][0] = t1; bh[2 * g + 1][1] = t3;
                ldsm_x4(uBl + off, t0, t1, t2, t3);
                bl[2 * g][0] = t0; bl[2 * g][1] = t2;
                bl[2 * g + 1][0] = t1; bl[2 * g + 1][1] = t3;
            }
#pragma unroll
            for (int mi = 0; mi < 2; mi++)
#pragma unroll
                for (int nj = 0; nj < 8; nj++) {
                    mma_bf16(acc[mi][nj], ah[mi], bh[nj]);
                    mma_bf16(acc[mi][nj], ah[mi], bl[nj]);
                    mma_bf16(acc[mi][nj], al[mi], bh[nj]);
                }
        }
    }

    // Epilogue: fp32 direct to C
#pragma unroll
    for (int mi = 0; mi < 2; mi++) {
#pragma unroll
        for (int nj = 0; nj < 8; nj++) {
            int row = m0 + m0w + mi * 16 + (lid >> 2);
            int col = n0 + n0w + nj * 8 + (lid & 3) * 2;
            float2 v0 = make_float2(acc[mi][nj][0], acc[mi][nj][1]);
            float2 v1 = make_float2(acc[mi][nj][2], acc[mi][nj][3]);
            *(float2*)&C[(long)row * N + col] = v0;
            *(float2*)&C[(long)(row + 8) * N + col] = v1;
        }
    }
}

// ---------------------------------------------------------------------------
// RoPE: in-place on [B,S,H,HD] with rotate_half pairing (i, i+32)
// ---------------------------------------------------------------------------
__global__ void rope_kernel(float* __restrict__ x,
                            const float* __restrict__ cosb,
                            const float* __restrict__ sinb,
                            int nheads, int total_pairs) {
    int idx = blockIdx.x * blockDim.x + threadIdx.x;
    if (idx >= total_pairs) return;
    int i = idx & 31;
    int h = (idx >> 5) % nheads;
    int s = (idx / (32 * nheads)) % SS;
    int b = idx / (32 * nheads * SS);
    long base = ((long)(b * SS + s) * nheads + h) * HD;
    float x1 = x[base + i];
    float x2 = x[base + i + 32];
    float c1 = cosb[s * HD + i];
    float s1 = sinb[s * HD + i];
    float c2 = cosb[s * HD + i + 32];
    float s2 = sinb[s * HD + i + 32];
    x[base + i]      = x1 * c1 - x2 * s1;
    x[base + i + 32] = x2 * c2 + x1 * s2;
}

// ---------------------------------------------------------------------------
// Flash attention (GQA), fp32: one q row per thread, 128 rows per block.
// ---------------------------------------------------------------------------
__global__ void __launch_bounds__(128) flash_attn(const float* __restrict__ Q,
                                                  const float* __restrict__ Kg,
                                                  const float* __restrict__ Vg,
                                                  float* __restrict__ O) {
    const int TK = 32;
    __shared__ float Ks[TK * HD];
    __shared__ float Vs[TK * HD];

    int tid = threadIdx.x;
    int h   = blockIdx.y;
    int b   = blockIdx.z;
    int row = blockIdx.x * 128 + tid;
    int kvh = h >> 2;  // NREP = 4

    const float scale = 0.125f;  // 1/sqrt(64)

    float qreg[HD];
    const float* qp = Q + ((long)(b * SS + row) * (NH * HD)) + h * HD;
#pragma unroll
    for (int d = 0; d < HD; d += 4) {
        float4 t = *(const float4*)(qp + d);
        qreg[d] = t.x; qreg[d + 1] = t.y; qreg[d + 2] = t.z; qreg[d + 3] = t.w;
    }

    float m = -INFINITY, l = 0.f;
    float acc[HD];
#pragma unroll
    for (int d = 0; d < HD; d++) acc[d] = 0.f;

    const float* kbase = Kg + (long)b * SS * (NKV * HD) + kvh * HD;
    const float* vbase = Vg + (long)b * SS * (NKV * HD) + kvh * HD;

    for (int j0 = 0; j0 < SS; j0 += TK) {
#pragma unroll
        for (int it = 0; it < 4; it++) {
            int fidx = (tid + it * 128) * 4;
            int jr = fidx / HD;
            int dc = fidx % HD;
            const float* ksrc = kbase + (long)(j0 + jr) * (NKV * HD) + dc;
            const float* vsrc = vbase + (long)(j0 + jr) * (NKV * HD) + dc;
            *(float4*)&Ks[fidx] = *(const float4*)ksrc;
            *(float4*)&Vs[fidx] = *(const float4*)vsrc;
        }
        __syncthreads();

        float sreg[TK];
#pragma unroll 4
        for (int j = 0; j < TK; j++) {
            float dot = 0.f;
#pragma unroll
            for (int d = 0; d < HD; d += 4) {
                float4 kv = *(const float4*)&Ks[j * HD + d];
                dot += qreg[d] * kv.x + qreg[d + 1] * kv.y +
                       qreg[d + 2] * kv.z + qreg[d + 3] * kv.w;
            }
            sreg[j] = dot * scale;
        }

        float mt = sreg[0];
#pragma unroll
        for (int j = 1; j < TK; j++) mt = fmaxf(mt, sreg[j]);
        float m_new = fmaxf(m, mt);
        float corr = __expf(m - m_new);
        float psum = 0.f;
#pragma unroll
        for (int j = 0; j < TK; j++) {
            sreg[j] = __expf(sreg[j] - m_new);
            psum += sreg[j];
        }
        l = l * corr + psum;
#pragma unroll
        for (int d = 0; d < HD; d++) acc[d] *= corr;
#pragma unroll 2
        for (int j = 0; j < TK; j++) {
            float p = sreg[j];
#pragma unroll
            for (int d = 0; d < HD; d += 4) {
                float4 vv = *(const float4*)&Vs[j * HD + d];
                acc[d]     += p * vv.x;
                acc[d + 1] += p * vv.y;
                acc[d + 2] += p * vv.z;
                acc[d + 3] += p * vv.w;
            }
        }
        m = m_new;
        __syncthreads();
    }

    float inv_l = 1.f / l;
    float* op = O + ((long)(b * SS + row) * (NH * HD)) + h * HD;
#pragma unroll
    for (int d = 0; d < HD; d += 4) {
        *(float4*)(op + d) = make_float4(acc[d] * inv_l, acc[d + 1] * inv_l,
                                         acc[d + 2] * inv_l, acc[d + 3] * inv_l);
    }
}

// ---------------------------------------------------------------------------
// Launch
// ---------------------------------------------------------------------------
extern "C" void kernel_launch(void* const* d_in, const int* in_sizes, int n_in,
                              void* d_out, int out_size) {
    const float* x    = (const float*)d_in[0];
    const float* cosb = (const float*)d_in[1];
    const float* sinb = (const float*)d_in[2];
    const float* wq   = (const float*)d_in[3];
    const float* wk   = (const float*)d_in[4];
    const float* wv   = (const float*)d_in[5];
    const float* wo   = (const float*)d_in[6];
    float* out = (float*)d_out;

    void *pq, *pk, *pv, *pa;
    cudaGetSymbolAddress(&pq, g_q);
    cudaGetSymbolAddress(&pk, g_k);
    cudaGetSymbolAddress(&pv, g_v);
    cudaGetSymbolAddress(&pa, g_attn);
    float* Q = (float*)pq;
    float* K = (float*)pk;
    float* V = (float*)pv;
    float* A = (float*)pa;

    void *pxh, *pxl, *pqh, *pql, *pkh, *pkl, *pvh, *pvl, *poh, *pol, *pah, *pal;
    cudaGetSymbolAddress(&pxh, g_x_hi);  cudaGetSymbolAddress(&pxl, g_x_lo);
    cudaGetSymbolAddress(&pqh, g_wq_hi); cudaGetSymbolAddress(&pql, g_wq_lo);
    cudaGetSymbolAddress(&pkh, g_wk_hi); cudaGetSymbolAddress(&pkl, g_wk_lo);
    cudaGetSymbolAddress(&pvh, g_wv_hi); cudaGetSymbolAddress(&pvl, g_wv_lo);
    cudaGetSymbolAddress(&poh, g_wo_hi); cudaGetSymbolAddress(&pol, g_wo_lo);
    cudaGetSymbolAddress(&pah, g_a_hi);  cudaGetSymbolAddress(&pal, g_a_lo);

    const int M = BB * SS;   // 4096
    const int HK = HIDD;     // 2048

    // Split inputs/weights into bf16 hi/lo
    const int nx  = M * HIDD;          // 8M
    const int nwq = NH * HD * HIDD;    // 4M
    const int nwk = NKV * HD * HIDD;   // 1M
    cvt_split<<<nx / 1024, 256>>>(x, (__nv_bfloat16*)pxh, (__nv_bfloat16*)pxl, nx);
    cvt_split<<<nwq / 1024, 256>>>(wq, (__nv_bfloat16*)pqh, (__nv_bfloat16*)pql, nwq);
    cvt_split<<<nwk / 1024, 256>>>(wk, (__nv_bfloat16*)pkh, (__nv_bfloat16*)pkl, nwk);
    cvt_split<<<nwk / 1024, 256>>>(wv, (__nv_bfloat16*)pvh, (__nv_bfloat16*)pvl, nwk);
    cvt_split<<<nwq / 1024, 256>>>(wo, (__nv_bfloat16*)poh, (__nv_bfloat16*)pol, nwq);

    // Projections (HMMA split-bf16)
    gemm_tc<<<dim3(NH * HD / 128, M / 128), 256>>>(
        (const __nv_bfloat16*)pxh, (const __nv_bfloat16*)pxl,
        (const __nv_bfloat16*)pqh, (const __nv_bfloat16*)pql, Q, M, NH * HD, HK);
    gemm_tc<<<dim3(NKV * HD / 128, M / 128), 256>>>(
        (const __nv_bfloat16*)pxh, (const __nv_bfloat16*)pxl,
        (const __nv_bfloat16*)pkh, (const __nv_bfloat16*)pkl, K, M, NKV * HD, HK);
    gemm_tc<<<dim3(NKV * HD / 128, M / 128), 256>>>(
        (const __nv_bfloat16*)pxh, (const __nv_bfloat16*)pxl,
        (const __nv_bfloat16*)pvh, (const __nv_bfloat16*)pvl, V, M, NKV * HD, HK);

    // RoPE
    int qpairs = BB * SS * NH * 32;
    int kpairs = BB * SS * NKV * 32;
    rope_kernel<<<(qpairs + 255) / 256, 256>>>(Q, cosb, sinb, NH, qpairs);
    rope_kernel<<<(kpairs + 255) / 256, 256>>>(K, cosb, sinb, NKV, kpairs);

    // Attention (fp32 flash)
    flash_attn<<<dim3(SS / 128, NH, BB), 128>>>(Q, K, V, A);

    // Output projection
    cvt_split<<<nx / 1024, 256>>>(A, (__nv_bfloat16*)pah, (__nv_bfloat16*)pal, nx);
    gemm_tc<<<dim3(HIDD / 128, M / 128), 256>>>(
        (const __nv_bfloat16*)pah, (const __nv_bfloat16*)pal,
        (const __nv_bfloat16*)poh, (const __nv_bfloat16*)pol, out, M, HIDD, HK);
}

// round 9
// speedup vs baseline: 3.1038x; 2.2341x over previous
#include <cuda_runtime.h>
#include <cuda_bf16.h>
#include <math.h>
#include <stdint.h>

// Problem constants
#define BB   2
#define SS   2048
#define HIDD 2048
#define NH   32
#define NKV  8
#define HD   64
#define NREP 4

// ---------------------------------------------------------------------------
// Device-global scratch (allocation-free rule)
// ---------------------------------------------------------------------------
__device__ float g_q[BB * SS * NH * HD];     // [B,S,NH*HD] fp32 (pre-RoPE)
__device__ float g_k[BB * SS * NKV * HD];
__device__ float g_v[BB * SS * NKV * HD];

// split-bf16 operands
__device__ __nv_bfloat16 g_x_hi[BB * SS * HIDD];
__device__ __nv_bfloat16 g_x_lo[BB * SS * HIDD];
__device__ __nv_bfloat16 g_wq_hi[NH * HD * HIDD];
__device__ __nv_bfloat16 g_wq_lo[NH * HD * HIDD];
__device__ __nv_bfloat16 g_wk_hi[NKV * HD * HIDD];
__device__ __nv_bfloat16 g_wk_lo[NKV * HD * HIDD];
__device__ __nv_bfloat16 g_wv_hi[NKV * HD * HIDD];
__device__ __nv_bfloat16 g_wv_lo[NKV * HD * HIDD];
__device__ __nv_bfloat16 g_wo_hi[HIDD * NH * HD];
__device__ __nv_bfloat16 g_wo_lo[HIDD * NH * HD];
__device__ __nv_bfloat16 g_a_hi[BB * SS * NH * HD];
__device__ __nv_bfloat16 g_a_lo[BB * SS * NH * HD];

// split-bf16 attention operands (post-RoPE)
__device__ __nv_bfloat16 g_qh[BB * SS * NH * HD];
__device__ __nv_bfloat16 g_ql[BB * SS * NH * HD];
__device__ __nv_bfloat16 g_kh[BB * SS * NKV * HD];
__device__ __nv_bfloat16 g_kl[BB * SS * NKV * HD];
__device__ __nv_bfloat16 g_vh[BB * SS * NKV * HD];
__device__ __nv_bfloat16 g_vl[BB * SS * NKV * HD];

// ---------------------------------------------------------------------------
// Helpers
// ---------------------------------------------------------------------------
__device__ __forceinline__ uint32_t smem_u32(const void* p) {
    uint32_t a;
    asm("{ .reg .u64 t; cvta.to.shared.u64 t, %1; cvt.u32.u64 %0, t; }"
        : "=r"(a) : "l"(p));
    return a;
}

// GEMM tiles: 128 rows x 32 bf16 (64B rows, 4 chunks)
__device__ __forceinline__ uint32_t sw_off(int row, int ch) {
    return (uint32_t)(row * 64 + ((ch ^ ((row >> 1) & 3)) << 4));
}
// Attention tiles: rows of 64 bf16 (128B rows, 8 chunks)
__device__ __forceinline__ uint32_t sw_off8(int row, int ch) {
    return (uint32_t)(row * 128 + ((ch ^ (row & 7)) << 4));
}

__device__ __forceinline__ void ldsm_x4(uint32_t addr, uint32_t& r0, uint32_t& r1,
                                        uint32_t& r2, uint32_t& r3) {
    asm volatile("ldmatrix.sync.aligned.m8n8.x4.shared.b16 {%0,%1,%2,%3}, [%4];"
                 : "=r"(r0), "=r"(r1), "=r"(r2), "=r"(r3) : "r"(addr));
}
__device__ __forceinline__ void ldsm_x4_t(uint32_t addr, uint32_t& r0, uint32_t& r1,
                                          uint32_t& r2, uint32_t& r3) {
    asm volatile("ldmatrix.sync.aligned.m8n8.x4.trans.shared.b16 {%0,%1,%2,%3}, [%4];"
                 : "=r"(r0), "=r"(r1), "=r"(r2), "=r"(r3) : "r"(addr));
}

__device__ __forceinline__ void mma_bf16(float* c, const uint32_t* a, const uint32_t* b) {
    asm volatile(
        "mma.sync.aligned.m16n8k16.row.col.f32.bf16.bf16.f32 "
        "{%0,%1,%2,%3}, {%4,%5,%6,%7}, {%8,%9}, {%0,%1,%2,%3};"
        : "+f"(c[0]), "+f"(c[1]), "+f"(c[2]), "+f"(c[3])
        : "r"(a[0]), "r"(a[1]), "r"(a[2]), "r"(a[3]), "r"(b[0]), "r"(b[1]));
}

__device__ __forceinline__ uint32_t pack_bf16(float a, float b) {
    __nv_bfloat162 t = __floats2bfloat162_rn(a, b);
    return *(uint32_t*)&t;
}

// ---------------------------------------------------------------------------
// Split fp32 -> (hi, lo) bf16
// ---------------------------------------------------------------------------
__global__ void cvt_split(const float* __restrict__ in,
                          __nv_bfloat16* __restrict__ hi,
                          __nv_bfloat16* __restrict__ lo, int n) {
    int i = (blockIdx.x * blockDim.x + threadIdx.x) * 4;
    if (i >= n) return;
    float4 f = *(const float4*)(in + i);
    __nv_bfloat16 h0 = __float2bfloat16(f.x);
    __nv_bfloat16 h1 = __float2bfloat16(f.y);
    __nv_bfloat16 h2 = __float2bfloat16(f.z);
    __nv_bfloat16 h3 = __float2bfloat16(f.w);
    __nv_bfloat16 l0 = __float2bfloat16(f.x - __bfloat162float(h0));
    __nv_bfloat16 l1 = __float2bfloat16(f.y - __bfloat162float(h1));
    __nv_bfloat16 l2 = __float2bfloat16(f.z - __bfloat162float(h2));
    __nv_bfloat16 l3 = __float2bfloat16(f.w - __bfloat162float(h3));
    __nv_bfloat162* hp = (__nv_bfloat162*)(hi + i);
    __nv_bfloat162* lp = (__nv_bfloat162*)(lo + i);
    hp[0] = __nv_bfloat162(h0, h1);
    hp[1] = __nv_bfloat162(h2, h3);
    lp[0] = __nv_bfloat162(l0, l1);
    lp[1] = __nv_bfloat162(l2, l3);
}

// ---------------------------------------------------------------------------
// Split-bf16 NT GEMM on HMMA (unchanged from R7 — verified)
// ---------------------------------------------------------------------------
__global__ void __launch_bounds__(256, 1)
gemm_tc(const __nv_bfloat16* __restrict__ Ahi, const __nv_bfloat16* __restrict__ Alo,
        const __nv_bfloat16* __restrict__ Bhi, const __nv_bfloat16* __restrict__ Blo,
        float* __restrict__ C, int M, int N, int K) {
    __shared__ __align__(16) char sAh[8192];
    __shared__ __align__(16) char sAl[8192];
    __shared__ __align__(16) char sBh[8192];
    __shared__ __align__(16) char sBl[8192];

    const int tid = threadIdx.x;
    const int wid = tid >> 5;
    const int lid = tid & 31;
    const int m0 = blockIdx.y * 128;
    const int n0 = blockIdx.x * 128;
    const int m0w = (wid >> 1) * 32;
    const int n0w = (wid & 1) * 64;

    const long ldb = (long)K * 2;
    const char* aH = (const char*)(Ahi + (long)m0 * K);
    const char* aL = (const char*)(Alo + (long)m0 * K);
    const char* bH = (const char*)(Bhi + (long)n0 * K);
    const char* bL = (const char*)(Blo + (long)n0 * K);

    const uint32_t uAh = smem_u32(sAh), uAl = smem_u32(sAl);
    const uint32_t uBh = smem_u32(sBh), uBl = smem_u32(sBl);

    const int r0 = tid >> 2, c0 = tid & 3;
    const int r1 = (tid + 256) >> 2, c1 = tid & 3;
    const uint32_t so0 = sw_off(r0, c0), so1 = sw_off(r1, c1);
    const long go0 = (long)r0 * ldb + c0 * 16;
    const long go1 = (long)r1 * ldb + c1 * 16;

    float acc[2][8][4];
#pragma unroll
    for (int i = 0; i < 2; i++)
#pragma unroll
        for (int j = 0; j < 8; j++)
#pragma unroll
            for (int v = 0; v < 4; v++) acc[i][j][v] = 0.f;

    uint4 pf[8];
    {
        pf[0] = *(const uint4*)(aH + go0); pf[1] = *(const uint4*)(aH + go1);
        pf[2] = *(const uint4*)(aL + go0); pf[3] = *(const uint4*)(aL + go1);
        pf[4] = *(const uint4*)(bH + go0); pf[5] = *(const uint4*)(bH + go1);
        pf[6] = *(const uint4*)(bL + go0); pf[7] = *(const uint4*)(bL + go1);
    }

    const int niter = K >> 5;
    for (int it = 0; it < niter; it++) {
        __syncthreads();
        *(uint4*)(sAh + so0) = pf[0]; *(uint4*)(sAh + so1) = pf[1];
        *(uint4*)(sAl + so0) = pf[2]; *(uint4*)(sAl + so1) = pf[3];
        *(uint4*)(sBh + so0) = pf[4]; *(uint4*)(sBh + so1) = pf[5];
        *(uint4*)(sBl + so0) = pf[6]; *(uint4*)(sBl + so1) = pf[7];
        __syncthreads();

        {
            const long kb = (it + 1 < niter) ? (long)(it + 1) * 64 : 0;
            pf[0] = *(const uint4*)(aH + go0 + kb); pf[1] = *(const uint4*)(aH + go1 + kb);
            pf[2] = *(const uint4*)(aL + go0 + kb); pf[3] = *(const uint4*)(aL + go1 + kb);
            pf[4] = *(const uint4*)(bH + go0 + kb); pf[5] = *(const uint4*)(bH + go1 + kb);
            pf[6] = *(const uint4*)(bL + go0 + kb); pf[7] = *(const uint4*)(bL + go1 + kb);
        }

#pragma unroll
        for (int ks = 0; ks < 2; ks++) {
            uint32_t ah[2][4], al[2][4], bh[8][2], bl[8][2];
            const int arow = m0w + (lid & 15);
            const int ach = ks * 2 + (lid >> 4);
#pragma unroll
            for (int mi = 0; mi < 2; mi++) {
                uint32_t off = sw_off(arow + mi * 16, ach);
                ldsm_x4(uAh + off, ah[mi][0], ah[mi][1], ah[mi][2], ah[mi][3]);
                ldsm_x4(uAl + off, al[mi][0], al[mi][1], al[mi][2], al[mi][3]);
            }
            const int brow = n0w + (lid & 15);
            const int bch = ks * 2 + (lid >> 4);
#pragma unroll
            for (int g = 0; g < 4; g++) {
                uint32_t off = sw_off(brow + g * 16, bch);
                uint32_t t0, t1, t2, t3;
                ldsm_x4(uBh + off, t0, t1, t2, t3);
                bh[2 * g][0] = t0; bh[2 * g][1] = t2;
                bh[2 * g + 1][0] = t1; bh[2 * g + 1][1] = t3;
                ldsm_x4(uBl + off, t0, t1, t2, t3);
                bl[2 * g][0] = t0; bl[2 * g][1] = t2;
                bl[2 * g + 1][0] = t1; bl[2 * g + 1][1] = t3;
            }
#pragma unroll
            for (int mi = 0; mi < 2; mi++)
#pragma unroll
                for (int nj = 0; nj < 8; nj++) {
                    mma_bf16(acc[mi][nj], ah[mi], bh[nj]);
                    mma_bf16(acc[mi][nj], ah[mi], bl[nj]);
                    mma_bf16(acc[mi][nj], al[mi], bh[nj]);
                }
        }
    }

#pragma unroll
    for (int mi = 0; mi < 2; mi++) {
#pragma unroll
        for (int nj = 0; nj < 8; nj++) {
            int row = m0 + m0w + mi * 16 + (lid >> 2);
            int col = n0 + n0w + nj * 8 + (lid & 3) * 2;
            *(float2*)&C[(long)row * N + col] = make_float2(acc[mi][nj][0], acc[mi][nj][1]);
            *(float2*)&C[(long)(row + 8) * N + col] = make_float2(acc[mi][nj][2], acc[mi][nj][3]);
        }
    }
}

// ---------------------------------------------------------------------------
// RoPE + split: reads fp32 [B,S,H,HD], writes hi/lo bf16 (rotate_half pairs)
// ---------------------------------------------------------------------------
__global__ void rope_split(const float* __restrict__ x,
                           const float* __restrict__ cosb,
                           const float* __restrict__ sinb,
                           __nv_bfloat16* __restrict__ hi,
                           __nv_bfloat16* __restrict__ lo,
                           int nheads, int total_pairs) {
    int idx = blockIdx.x * blockDim.x + threadIdx.x;
    if (idx >= total_pairs) return;
    int i = idx & 31;
    int h = (idx >> 5) % nheads;
    int s = (idx / (32 * nheads)) % SS;
    int b = idx / (32 * nheads * SS);
    long base = ((long)(b * SS + s) * nheads + h) * HD;
    float x1 = x[base + i];
    float x2 = x[base + i + 32];
    float c1 = cosb[s * HD + i];
    float s1 = sinb[s * HD + i];
    float c2 = cosb[s * HD + i + 32];
    float s2 = sinb[s * HD + i + 32];
    float y1 = x1 * c1 - x2 * s1;
    float y2 = x2 * c2 + x1 * s2;
    __nv_bfloat16 h1 = __float2bfloat16(y1);
    __nv_bfloat16 h2 = __float2bfloat16(y2);
    hi[base + i]      = h1;
    hi[base + i + 32] = h2;
    lo[base + i]      = __float2bfloat16(y1 - __bfloat162float(h1));
    lo[base + i + 32] = __float2bfloat16(y2 - __bfloat162float(h2));
}

// ---------------------------------------------------------------------------
// Flash attention on HMMA, split-bf16 everywhere.
// 128 q-rows/CTA (8 warps x 16 rows), K/V tiles of 64 keys in swizzled SMEM.
// grid = (S/128, NH, B), 256 threads.
// ---------------------------------------------------------------------------
__global__ void __launch_bounds__(256, 1)
flash_attn_tc(const __nv_bfloat16* __restrict__ Qh, const __nv_bfloat16* __restrict__ Ql,
              const __nv_bfloat16* __restrict__ Kh, const __nv_bfloat16* __restrict__ Kl,
              const __nv_bfloat16* __restrict__ Vh, const __nv_bfloat16* __restrict__ Vl,
              __nv_bfloat16* __restrict__ Oh, __nv_bfloat16* __restrict__ Ol) {
    __shared__ __align__(16) char sm[32768];
    const int tid = threadIdx.x;
    const int wid = tid >> 5;
    const int lid = tid & 31;
    const int h = blockIdx.y;
    const int b = blockIdx.z;
    const int s0 = blockIdx.x * 128;
    const int kvh = h >> 2;   // NREP = 4
    const float scale = 0.125f;

    const uint32_t uS = smem_u32(sm);

    // ---- Phase 1: stage Q tile (128 x 64 bf16, hi at 0 / lo at 16384), grab frags
    {
        const char* gqh = (const char*)(Qh + (((long)(b * SS + s0)) * NH + h) * HD);
        const char* gql = (const char*)(Ql + (((long)(b * SS + s0)) * NH + h) * HD);
        const long qstr = (long)NH * HD * 2;   // 4096 B
#pragma unroll
        for (int i = 0; i < 4; i++) {
            int c = tid + i * 256;       // 0..1023 chunk idx
            int row = c >> 3, ch = c & 7;
            uint32_t so = sw_off8(row, ch);
            *(uint4*)(sm + so)         = *(const uint4*)(gqh + (long)row * qstr + ch * 16);
            *(uint4*)(sm + 16384 + so) = *(const uint4*)(gql + (long)row * qstr + ch * 16);
        }
    }
    __syncthreads();

    uint32_t qhf[4][4], qlf[4][4];
    {
        const int arow = wid * 16 + (lid & 15);
#pragma unroll
        for (int ks = 0; ks < 4; ks++) {
            int ch = 2 * ks + (lid >> 4);
            uint32_t off = sw_off8(arow, ch);
            ldsm_x4(uS + off, qhf[ks][0], qhf[ks][1], qhf[ks][2], qhf[ks][3]);
            ldsm_x4(uS + 16384 + off, qlf[ks][0], qlf[ks][1], qlf[ks][2], qlf[ks][3]);
        }
    }
    __syncthreads();

    // ---- State
    float o[8][4];
#pragma unroll
    for (int j = 0; j < 8; j++)
#pragma unroll
        for (int v = 0; v < 4; v++) o[j][v] = 0.f;
    float m0 = -INFINITY, m1 = -INFINITY, l0 = 0.f, l1 = 0.f;

    // SMEM: Kh@0  Kl@8192  Vh@16384  Vl@24576 (64 rows x 128B each)
    const char* gkh = (const char*)(Kh + (((long)(b * SS)) * NKV + kvh) * HD);
    const char* gkl = (const char*)(Kl + (((long)(b * SS)) * NKV + kvh) * HD);
    const char* gvh = (const char*)(Vh + (((long)(b * SS)) * NKV + kvh) * HD);
    const char* gvl = (const char*)(Vl + (((long)(b * SS)) * NKV + kvh) * HD);
    const long kvstr = (long)NKV * HD * 2;   // 1024 B

    for (int j0 = 0; j0 < SS; j0 += 64) {
        // cooperative load K/V tiles (hi+lo): 4 arrays x 512 chunks
#pragma unroll
        for (int i = 0; i < 2; i++) {
            int c = tid + i * 256;       // 0..511
            int row = c >> 3, ch = c & 7;
            uint32_t so = sw_off8(row, ch);
            long go = (long)(j0 + row) * kvstr + ch * 16;
            *(uint4*)(sm + so)         = *(const uint4*)(gkh + go);
            *(uint4*)(sm + 8192 + so)  = *(const uint4*)(gkl + go);
            *(uint4*)(sm + 16384 + so) = *(const uint4*)(gvh + go);
            *(uint4*)(sm + 24576 + so) = *(const uint4*)(gvl + go);
        }
        __syncthreads();

        // ---- scores: S = Q * K^T  (16 x 64 per warp)
        float sc[8][4];
#pragma unroll
        for (int j = 0; j < 8; j++)
#pragma unroll
            for (int v = 0; v < 4; v++) sc[j][v] = 0.f;

#pragma unroll
        for (int ks = 0; ks < 4; ks++) {
            uint32_t bh[8][2], bl[8][2];
            const int brow = lid & 15;
            const int bch = 2 * ks + (lid >> 4);
#pragma unroll
            for (int g = 0; g < 4; g++) {
                int r = g * 16 + brow;
                uint32_t off = sw_off8(r, bch);
                uint32_t t0, t1, t2, t3;
                ldsm_x4(uS + off, t0, t1, t2, t3);
                bh[2 * g][0] = t0; bh[2 * g][1] = t2;
                bh[2 * g + 1][0] = t1; bh[2 * g + 1][1] = t3;
                ldsm_x4(uS + 8192 + off, t0, t1, t2, t3);
                bl[2 * g][0] = t0; bl[2 * g][1] = t2;
                bl[2 * g + 1][0] = t1; bl[2 * g + 1][1] = t3;
            }
#pragma unroll
            for (int nj = 0; nj < 8; nj++) {
                mma_bf16(sc[nj], qhf[ks], bh[nj]);
                mma_bf16(sc[nj], qhf[ks], bl[nj]);
                mma_bf16(sc[nj], qlf[ks], bh[nj]);
            }
        }

        // ---- online softmax (rows r = lid>>2 and r+8; 4 lanes per row)
        float mx0 = -INFINITY, mx1 = -INFINITY;
#pragma unroll
        for (int nj = 0; nj < 8; nj++) {
            sc[nj][0] *= scale; sc[nj][1] *= scale;
            sc[nj][2] *= scale; sc[nj][3] *= scale;
            mx0 = fmaxf(mx0, fmaxf(sc[nj][0], sc[nj][1]));
            mx1 = fmaxf(mx1, fmaxf(sc[nj][2], sc[nj][3]));
        }
        mx0 = fmaxf(mx0, __shfl_xor_sync(0xffffffffu, mx0, 1));
        mx0 = fmaxf(mx0, __shfl_xor_sync(0xffffffffu, mx0, 2));
        mx1 = fmaxf(mx1, __shfl_xor_sync(0xffffffffu, mx1, 1));
        mx1 = fmaxf(mx1, __shfl_xor_sync(0xffffffffu, mx1, 2));

        float mn0 = fmaxf(m0, mx0), mn1 = fmaxf(m1, mx1);
        float cor0 = __expf(m0 - mn0), cor1 = __expf(m1 - mn1);
        m0 = mn0; m1 = mn1;

        float sum0 = 0.f, sum1 = 0.f;
        uint32_t pah[4][4], pal[4][4];
#pragma unroll
        for (int nj = 0; nj < 8; nj++) {
            float p00 = __expf(sc[nj][0] - mn0);
            float p01 = __expf(sc[nj][1] - mn0);
            float p10 = __expf(sc[nj][2] - mn1);
            float p11 = __expf(sc[nj][3] - mn1);
            sum0 += p00 + p01;
            sum1 += p10 + p11;
            __nv_bfloat16 h00 = __float2bfloat16(p00), h01 = __float2bfloat16(p01);
            __nv_bfloat16 h10 = __float2bfloat16(p10), h11 = __float2bfloat16(p11);
            int ks = nj >> 1, half = nj & 1;
            pah[ks][half * 2]     = pack_bf16(__bfloat162float(h00), __bfloat162float(h01));
            pah[ks][half * 2 + 1] = pack_bf16(__bfloat162float(h10), __bfloat162float(h11));
            pal[ks][half * 2]     = pack_bf16(p00 - __bfloat162float(h00),
                                              p01 - __bfloat162float(h01));
            pal[ks][half * 2 + 1] = pack_bf16(p10 - __bfloat162float(h10),
                                              p11 - __bfloat162float(h11));
        }
        sum0 += __shfl_xor_sync(0xffffffffu, sum0, 1);
        sum0 += __shfl_xor_sync(0xffffffffu, sum0, 2);
        sum1 += __shfl_xor_sync(0xffffffffu, sum1, 1);
        sum1 += __shfl_xor_sync(0xffffffffu, sum1, 2);
        l0 = l0 * cor0 + sum0;
        l1 = l1 * cor1 + sum1;

#pragma unroll
        for (int nj = 0; nj < 8; nj++) {
            o[nj][0] *= cor0; o[nj][1] *= cor0;
            o[nj][2] *= cor1; o[nj][3] *= cor1;
        }

        // ---- O += P * V   (V as B-fragments via ldmatrix.trans)
#pragma unroll
        for (int ks = 0; ks < 4; ks++) {
            uint32_t vh[8][2], vl[8][2];
            const int krow = ks * 16 + (lid & 15);
#pragma unroll
            for (int g = 0; g < 4; g++) {
                int ch = 2 * g + (lid >> 4);
                uint32_t off = sw_off8(krow, ch);
                uint32_t t0, t1, t2, t3;
                ldsm_x4_t(uS + 16384 + off, t0, t1, t2, t3);
                vh[2 * g][0] = t0; vh[2 * g][1] = t1;
                vh[2 * g + 1][0] = t2; vh[2 * g + 1][1] = t3;
                ldsm_x4_t(uS + 24576 + off, t0, t1, t2, t3);
                vl[2 * g][0] = t0; vl[2 * g][1] = t1;
                vl[2 * g + 1][0] = t2; vl[2 * g + 1][1] = t3;
            }
#pragma unroll
            for (int nj = 0; nj < 8; nj++) {
                mma_bf16(o[nj], pah[ks], vh[nj]);
                mma_bf16(o[nj], pah[ks], vl[nj]);
                mma_bf16(o[nj], pal[ks], vh[nj]);
            }
        }
        __syncthreads();
    }

    // ---- epilogue: normalize, split to hi/lo bf16, store [B,S,H,HD]
    float inv0 = 1.f / l0, inv1 = 1.f / l1;
    int row0 = s0 + wid * 16 + (lid >> 2);
#pragma unroll
    for (int nj = 0; nj < 8; nj++) {
        int col = nj * 8 + (lid & 3) * 2;
        float v00 = o[nj][0] * inv0, v01 = o[nj][1] * inv0;
        float v10 = o[nj][2] * inv1, v11 = o[nj][3] * inv1;
        long a0 = (((long)(b * SS + row0)) * NH + h) * HD + col;
        long a1 = (((long)(b * SS + row0 + 8)) * NH + h) * HD + col;
        __nv_bfloat16 h00 = __float2bfloat16(v00), h01 = __float2bfloat16(v01);
        __nv_bfloat16 h10 = __float2bfloat16(v10), h11 = __float2bfloat16(v11);
        *(uint32_t*)(Oh + a0) = pack_bf16(__bfloat162float(h00), __bfloat162float(h01));
        *(uint32_t*)(Oh + a1) = pack_bf16(__bfloat162float(h10), __bfloat162float(h11));
        *(uint32_t*)(Ol + a0) = pack_bf16(v00 - __bfloat162float(h00),
                                          v01 - __bfloat162float(h01));
        *(uint32_t*)(Ol + a1) = pack_bf16(v10 - __bfloat162float(h10),
                                          v11 - __bfloat162float(h11));
    }
}

// ---------------------------------------------------------------------------
// Launch
// ---------------------------------------------------------------------------
extern "C" void kernel_launch(void* const* d_in, const int* in_sizes, int n_in,
                              void* d_out, int out_size) {
    const float* x    = (const float*)d_in[0];
    const float* cosb = (const float*)d_in[1];
    const float* sinb = (const float*)d_in[2];
    const float* wq   = (const float*)d_in[3];
    const float* wk   = (const float*)d_in[4];
    const float* wv   = (const float*)d_in[5];
    const float* wo   = (const float*)d_in[6];
    float* out = (float*)d_out;

    void *pq, *pk, *pv;
    cudaGetSymbolAddress(&pq, g_q);
    cudaGetSymbolAddress(&pk, g_k);
    cudaGetSymbolAddress(&pv, g_v);
    float* Q = (float*)pq;
    float* K = (float*)pk;
    float* V = (float*)pv;

    void *pxh, *pxl, *pqh2, *pql2, *pkh2, *pkl2, *pvh2, *pvl2, *poh, *pol, *pah, *pal;
    cudaGetSymbolAddress(&pxh, g_x_hi);  cudaGetSymbolAddress(&pxl, g_x_lo);
    cudaGetSymbolAddress(&pqh2, g_wq_hi); cudaGetSymbolAddress(&pql2, g_wq_lo);
    cudaGetSymbolAddress(&pkh2, g_wk_hi); cudaGetSymbolAddress(&pkl2, g_wk_lo);
    cudaGetSymbolAddress(&pvh2, g_wv_hi); cudaGetSymbolAddress(&pvl2, g_wv_lo);
    cudaGetSymbolAddress(&poh, g_wo_hi); cudaGetSymbolAddress(&pol, g_wo_lo);
    cudaGetSymbolAddress(&pah, g_a_hi);  cudaGetSymbolAddress(&pal, g_a_lo);

    void *qh, *ql, *kh, *kl, *vh, *vl;
    cudaGetSymbolAddress(&qh, g_qh); cudaGetSymbolAddress(&ql, g_ql);
    cudaGetSymbolAddress(&kh, g_kh); cudaGetSymbolAddress(&kl, g_kl);
    cudaGetSymbolAddress(&vh, g_vh); cudaGetSymbolAddress(&vl, g_vl);

    const int M = BB * SS;   // 4096
    const int HK = HIDD;     // 2048

    // Split inputs/weights
    const int nx  = M * HIDD;          // 8M
    const int nwq = NH * HD * HIDD;    // 4M
    const int nwk = NKV * HD * HIDD;   // 1M
    cvt_split<<<nx / 1024, 256>>>(x, (__nv_bfloat16*)pxh, (__nv_bfloat16*)pxl, nx);
    cvt_split<<<nwq / 1024, 256>>>(wq, (__nv_bfloat16*)pqh2, (__nv_bfloat16*)pql2, nwq);
    cvt_split<<<nwk / 1024, 256>>>(wk, (__nv_bfloat16*)pkh2, (__nv_bfloat16*)pkl2, nwk);
    cvt_split<<<nwk / 1024, 256>>>(wv, (__nv_bfloat16*)pvh2, (__nv_bfloat16*)pvl2, nwk);
    cvt_split<<<nwq / 1024, 256>>>(wo, (__nv_bfloat16*)poh, (__nv_bfloat16*)pol, nwq);

    // Projections (HMMA split-bf16)
    gemm_tc<<<dim3(NH * HD / 128, M / 128), 256>>>(
        (const __nv_bfloat16*)pxh, (const __nv_bfloat16*)pxl,
        (const __nv_bfloat16*)pqh2, (const __nv_bfloat16*)pql2, Q, M, NH * HD, HK);
    gemm_tc<<<dim3(NKV * HD / 128, M / 128), 256>>>(
        (const __nv_bfloat16*)pxh, (const __nv_bfloat16*)pxl,
        (const __nv_bfloat16*)pkh2, (const __nv_bfloat16*)pkl2, K, M, NKV * HD, HK);
    gemm_tc<<<dim3(NKV * HD / 128, M / 128), 256>>>(
        (const __nv_bfloat16*)pxh, (const __nv_bfloat16*)pxl,
        (const __nv_bfloat16*)pvh2, (const __nv_bfloat16*)pvl2, V, M, NKV * HD, HK);

    // RoPE + split (Q, K); plain split (V)
    int qpairs = BB * SS * NH * 32;
    int kpairs = BB * SS * NKV * 32;
    rope_split<<<(qpairs + 255) / 256, 256>>>(Q, cosb, sinb,
        (__nv_bfloat16*)qh, (__nv_bfloat16*)ql, NH, qpairs);
    rope_split<<<(kpairs + 255) / 256, 256>>>(K, cosb, sinb,
        (__nv_bfloat16*)kh, (__nv_bfloat16*)kl, NKV, kpairs);
    const int nv = BB * SS * NKV * HD;  // 2M
    cvt_split<<<nv / 1024, 256>>>(V, (__nv_bfloat16*)vh, (__nv_bfloat16*)vl, nv);

    // Attention (HMMA flash, split-bf16) -> writes hi/lo directly
    flash_attn_tc<<<dim3(SS / 128, NH, BB), 256>>>(
        (const __nv_bfloat16*)qh, (const __nv_bfloat16*)ql,
        (const __nv_bfloat16*)kh, (const __nv_bfloat16*)kl,
        (const __nv_bfloat16*)vh, (const __nv_bfloat16*)vl,
        (__nv_bfloat16*)pah, (__nv_bfloat16*)pal);

    // Output projection
    gemm_tc<<<dim3(HIDD / 128, M / 128), 256>>>(
        (const __nv_bfloat16*)pah, (const __nv_bfloat16*)pal,
        (const __nv_bfloat16*)poh, (const __nv_bfloat16*)pol, out, M, HIDD, HK);
}

// round 14
// speedup vs baseline: 3.1586x; 1.0176x over previous
#include <cuda_runtime.h>
#include <cuda_bf16.h>
#include <math.h>
#include <stdint.h>

// Problem constants
#define BB   2
#define SS   2048
#define HIDD 2048
#define NH   32
#define NKV  8
#define HD   64
#define NREP 4

// ---------------------------------------------------------------------------
// Device-global scratch (allocation-free rule)
// ---------------------------------------------------------------------------
__device__ float g_q[BB * SS * NH * HD];     // fp32 pre-RoPE
__device__ float g_k[BB * SS * NKV * HD];
__device__ float g_v[BB * SS * NKV * HD];

__device__ __nv_bfloat16 g_x_hi[BB * SS * HIDD];
__device__ __nv_bfloat16 g_x_lo[BB * SS * HIDD];
__device__ __nv_bfloat16 g_wq_hi[NH * HD * HIDD];
__device__ __nv_bfloat16 g_wq_lo[NH * HD * HIDD];
__device__ __nv_bfloat16 g_wk_hi[NKV * HD * HIDD];
__device__ __nv_bfloat16 g_wk_lo[NKV * HD * HIDD];
__device__ __nv_bfloat16 g_wv_hi[NKV * HD * HIDD];
__device__ __nv_bfloat16 g_wv_lo[NKV * HD * HIDD];
__device__ __nv_bfloat16 g_wo_hi[HIDD * NH * HD];
__device__ __nv_bfloat16 g_wo_lo[HIDD * NH * HD];
__device__ __nv_bfloat16 g_a_hi[BB * SS * NH * HD];
__device__ __nv_bfloat16 g_a_lo[BB * SS * NH * HD];

__device__ __nv_bfloat16 g_qh[BB * SS * NH * HD];
__device__ __nv_bfloat16 g_ql[BB * SS * NH * HD];
__device__ __nv_bfloat16 g_kh[BB * SS * NKV * HD];
__device__ __nv_bfloat16 g_kl[BB * SS * NKV * HD];
__device__ __nv_bfloat16 g_vh[BB * SS * NKV * HD];
__device__ __nv_bfloat16 g_vl[BB * SS * NKV * HD];

// ---------------------------------------------------------------------------
// Helpers
// ---------------------------------------------------------------------------
__device__ __forceinline__ uint32_t smem_u32(const void* p) {
    uint32_t a;
    asm("{ .reg .u64 t; cvta.to.shared.u64 t, %1; cvt.u32.u64 %0, t; }"
        : "=r"(a) : "l"(p));
    return a;
}

// GEMM tiles: 128 rows x 32 bf16 (64B rows, 4 chunks)
__device__ __forceinline__ uint32_t sw_off(int row, int ch) {
    return (uint32_t)(row * 64 + ((ch ^ ((row >> 1) & 3)) << 4));
}
// Attention tiles: rows of 64 bf16 (128B rows, 8 chunks)
__device__ __forceinline__ uint32_t sw_off8(int row, int ch) {
    return (uint32_t)(row * 128 + ((ch ^ (row & 7)) << 4));
}

__device__ __forceinline__ void ldsm_x4(uint32_t addr, uint32_t& r0, uint32_t& r1,
                                        uint32_t& r2, uint32_t& r3) {
    asm volatile("ldmatrix.sync.aligned.m8n8.x4.shared.b16 {%0,%1,%2,%3}, [%4];"
                 : "=r"(r0), "=r"(r1), "=r"(r2), "=r"(r3) : "r"(addr));
}
__device__ __forceinline__ void ldsm_x4_t(uint32_t addr, uint32_t& r0, uint32_t& r1,
                                          uint32_t& r2, uint32_t& r3) {
    asm volatile("ldmatrix.sync.aligned.m8n8.x4.trans.shared.b16 {%0,%1,%2,%3}, [%4];"
                 : "=r"(r0), "=r"(r1), "=r"(r2), "=r"(r3) : "r"(addr));
}

__device__ __forceinline__ void mma_bf16(float* c, const uint32_t* a, const uint32_t* b) {
    asm volatile(
        "mma.sync.aligned.m16n8k16.row.col.f32.bf16.bf16.f32 "
        "{%0,%1,%2,%3}, {%4,%5,%6,%7}, {%8,%9}, {%0,%1,%2,%3};"
        : "+f"(c[0]), "+f"(c[1]), "+f"(c[2]), "+f"(c[3])
        : "r"(a[0]), "r"(a[1]), "r"(a[2]), "r"(a[3]), "r"(b[0]), "r"(b[1]));
}

__device__ __forceinline__ uint32_t pack_bf16(float a, float b) {
    __nv_bfloat162 t = __floats2bfloat162_rn(a, b);
    return *(uint32_t*)&t;
}

__device__ __forceinline__ void cp_async16(uint32_t saddr, const void* g) {
    asm volatile("cp.async.cg.shared.global [%0], [%1], 16;" :: "r"(saddr), "l"(g));
}
#define CP_COMMIT() asm volatile("cp.async.commit_group;")
#define CP_WAIT(n)  asm volatile("cp.async.wait_group %0;" :: "n"(n))

// ---------------------------------------------------------------------------
// Split fp32 -> (hi, lo) bf16
// ---------------------------------------------------------------------------
__global__ void cvt_split(const float* __restrict__ in,
                          __nv_bfloat16* __restrict__ hi,
                          __nv_bfloat16* __restrict__ lo, int n) {
    int i = (blockIdx.x * blockDim.x + threadIdx.x) * 4;
    if (i >= n) return;
    float4 f = *(const float4*)(in + i);
    __nv_bfloat16 h0 = __float2bfloat16(f.x);
    __nv_bfloat16 h1 = __float2bfloat16(f.y);
    __nv_bfloat16 h2 = __float2bfloat16(f.z);
    __nv_bfloat16 h3 = __float2bfloat16(f.w);
    __nv_bfloat16 l0 = __float2bfloat16(f.x - __bfloat162float(h0));
    __nv_bfloat16 l1 = __float2bfloat16(f.y - __bfloat162float(h1));
    __nv_bfloat16 l2 = __float2bfloat16(f.z - __bfloat162float(h2));
    __nv_bfloat16 l3 = __float2bfloat16(f.w - __bfloat162float(h3));
    __nv_bfloat162* hp = (__nv_bfloat162*)(hi + i);
    __nv_bfloat162* lp = (__nv_bfloat162*)(lo + i);
    hp[0] = __nv_bfloat162(h0, h1);
    hp[1] = __nv_bfloat162(h2, h3);
    lp[0] = __nv_bfloat162(l0, l1);
    lp[1] = __nv_bfloat162(l2, l3);
}

// ---------------------------------------------------------------------------
// Pipelined split-bf16 GEMM body. cp.async 2-stage double buffer.
// C is pre-offset to (m0, n0); aH/aL pre-offset to row m0; bH/bL to row n0.
// SMEM per stage (32KB): Ah@0 Al@8192 Bh@16384 Bl@24576; stage1 at +32768.
// ---------------------------------------------------------------------------
__device__ __forceinline__ void gemm_body(
    const char* __restrict__ aH, const char* __restrict__ aL,
    const char* __restrict__ bH, const char* __restrict__ bL,
    float* __restrict__ C, int ldc, int K, char* sm) {
    const int tid = threadIdx.x;
    const int wid = tid >> 5;
    const int lid = tid & 31;
    const int m0w = (wid >> 1) * 32;
    const int n0w = (wid & 1) * 64;
    const long ldb = (long)K * 2;

    const int r0 = tid >> 2, c0 = tid & 3;
    const int r1 = r0 + 64;
    const uint32_t so0 = sw_off(r0, c0), so1 = sw_off(r1, c0);
    const long go0 = (long)r0 * ldb + c0 * 16;
    const long go1 = (long)r1 * ldb + c0 * 16;

    const uint32_t uS = smem_u32(sm);

    float acc[2][8][4];
#pragma unroll
    for (int i = 0; i < 2; i++)
#pragma unroll
        for (int j = 0; j < 8; j++)
#pragma unroll
            for (int v = 0; v < 4; v++) acc[i][j][v] = 0.f;

    const int niter = K >> 5;

    // issue stage 0
    {
        const uint32_t sb = uS;
        cp_async16(sb + so0, aH + go0);          cp_async16(sb + so1, aH + go1);
        cp_async16(sb + 8192 + so0, aL + go0);   cp_async16(sb + 8192 + so1, aL + go1);
        cp_async16(sb + 16384 + so0, bH + go0);  cp_async16(sb + 16384 + so1, bH + go1);
        cp_async16(sb + 24576 + so0, bL + go0);  cp_async16(sb + 24576 + so1, bL + go1);
        CP_COMMIT();
    }

    for (int it = 0; it < niter; it++) {
        if (it + 1 < niter) {
            const uint32_t sb = uS + ((it + 1) & 1) * 32768;
            const long kb = (long)(it + 1) * 64;
            cp_async16(sb + so0, aH + go0 + kb);          cp_async16(sb + so1, aH + go1 + kb);
            cp_async16(sb + 8192 + so0, aL + go0 + kb);   cp_async16(sb + 8192 + so1, aL + go1 + kb);
            cp_async16(sb + 16384 + so0, bH + go0 + kb);  cp_async16(sb + 16384 + so1, bH + go1 + kb);
            cp_async16(sb + 24576 + so0, bL + go0 + kb);  cp_async16(sb + 24576 + so1, bL + go1 + kb);
            CP_COMMIT();
            CP_WAIT(1);
        } else {
            CP_WAIT(0);
        }
        __syncthreads();

        const uint32_t uAh = uS + (it & 1) * 32768;
        const uint32_t uAl = uAh + 8192;
        const uint32_t uBh = uAh + 16384;
        const uint32_t uBl = uAh + 24576;

#pragma unroll
        for (int ks = 0; ks < 2; ks++) {
            uint32_t ah[2][4], al[2][4], bh[8][2], bl[8][2];
            const int arow = m0w + (lid & 15);
            const int ach = ks * 2 + (lid >> 4);
#pragma unroll
            for (int mi = 0; mi < 2; mi++) {
                uint32_t off = sw_off(arow + mi * 16, ach);
                ldsm_x4(uAh + off, ah[mi][0], ah[mi][1], ah[mi][2], ah[mi][3]);
                ldsm_x4(uAl + off, al[mi][0], al[mi][1], al[mi][2], al[mi][3]);
            }
            const int brow = n0w + (lid & 15);
            const int bch = ks * 2 + (lid >> 4);
#pragma unroll
            for (int g = 0; g < 4; g++) {
                uint32_t off = sw_off(brow + g * 16, bch);
                uint32_t t0, t1, t2, t3;
                ldsm_x4(uBh + off, t0, t1, t2, t3);
                bh[2 * g][0] = t0; bh[2 * g][1] = t2;
                bh[2 * g + 1][0] = t1; bh[2 * g + 1][1] = t3;
                ldsm_x4(uBl + off, t0, t1, t2, t3);
                bl[2 * g][0] = t0; bl[2 * g][1] = t2;
                bl[2 * g + 1][0] = t1; bl[2 * g + 1][1] = t3;
            }
#pragma unroll
            for (int mi = 0; mi < 2; mi++)
#pragma unroll
                for (int nj = 0; nj < 8; nj++) {
                    mma_bf16(acc[mi][nj], ah[mi], bh[nj]);
                    mma_bf16(acc[mi][nj], ah[mi], bl[nj]);
                    mma_bf16(acc[mi][nj], al[mi], bh[nj]);
                }
        }
        __syncthreads();
    }

#pragma unroll
    for (int mi = 0; mi < 2; mi++) {
#pragma unroll
        for (int nj = 0; nj < 8; nj++) {
            int row = m0w + mi * 16 + (lid >> 2);
            int col = n0w + nj * 8 + (lid & 3) * 2;
            *(float2*)&C[(long)row * ldc + col] = make_float2(acc[mi][nj][0], acc[mi][nj][1]);
            *(float2*)&C[(long)(row + 8) * ldc + col] = make_float2(acc[mi][nj][2], acc[mi][nj][3]);
        }
    }
}

// ---------------------------------------------------------------------------
// Fused Q/K/V projection GEMM. grid = (24, M/128).
// Tiles 0-15 -> Q (N=2048), 16-19 -> K (N=512), 20-23 -> V (N=512).
// ---------------------------------------------------------------------------
__global__ void __launch_bounds__(256, 1)
gemm_qkv(const __nv_bfloat16* __restrict__ Xh, const __nv_bfloat16* __restrict__ Xl,
         const __nv_bfloat16* __restrict__ Wqh, const __nv_bfloat16* __restrict__ Wql,
         const __nv_bfloat16* __restrict__ Wkh, const __nv_bfloat16* __restrict__ Wkl,
         const __nv_bfloat16* __restrict__ Wvh, const __nv_bfloat16* __restrict__ Wvl,
         float* __restrict__ Q, float* __restrict__ K, float* __restrict__ V) {
    extern __shared__ __align__(16) char sm[];
    const int bx = blockIdx.x;
    const int m0 = blockIdx.y * 128;
    const int KK = HIDD;

    const __nv_bfloat16 *bh, *bl;
    float* C;
    int ldc, n0;
    if (bx < 16)      { bh = Wqh; bl = Wql; C = Q; ldc = NH * HD;  n0 = bx * 128; }
    else if (bx < 20) { bh = Wkh; bl = Wkl; C = K; ldc = NKV * HD; n0 = (bx - 16) * 128; }
    else              { bh = Wvh; bl = Wvl; C = V; ldc = NKV * HD; n0 = (bx - 20) * 128; }

    gemm_body((const char*)(Xh + (long)m0 * KK), (const char*)(Xl + (long)m0 * KK),
              (const char*)(bh + (long)n0 * KK), (const char*)(bl + (long)n0 * KK),
              C + (long)m0 * ldc + n0, ldc, KK, sm);
}

// ---------------------------------------------------------------------------
// Generic NT GEMM (output projection). grid = (N/128, M/128).
// ---------------------------------------------------------------------------
__global__ void __launch_bounds__(256, 1)
gemm_tc(const __nv_bfloat16* __restrict__ Ahi, const __nv_bfloat16* __restrict__ Alo,
        const __nv_bfloat16* __restrict__ Bhi, const __nv_bfloat16* __restrict__ Blo,
        float* __restrict__ C, int M, int N, int K) {
    extern __shared__ __align__(16) char sm[];
    const int m0 = blockIdx.y * 128;
    const int n0 = blockIdx.x * 128;
    gemm_body((const char*)(Ahi + (long)m0 * K), (const char*)(Alo + (long)m0 * K),
              (const char*)(Bhi + (long)n0 * K), (const char*)(Blo + (long)n0 * K),
              C + (long)m0 * N + n0, N, K, sm);
}

// ---------------------------------------------------------------------------
// RoPE + split
// ---------------------------------------------------------------------------
__global__ void rope_split(const float* __restrict__ x,
                           const float* __restrict__ cosb,
                           const float* __restrict__ sinb,
                           __nv_bfloat16* __restrict__ hi,
                           __nv_bfloat16* __restrict__ lo,
                           int nheads, int total_pairs) {
    int idx = blockIdx.x * blockDim.x + threadIdx.x;
    if (idx >= total_pairs) return;
    int i = idx & 31;
    int h = (idx >> 5) % nheads;
    int s = (idx / (32 * nheads)) % SS;
    int b = idx / (32 * nheads * SS);
    long base = ((long)(b * SS + s) * nheads + h) * HD;
    float x1 = x[base + i];
    float x2 = x[base + i + 32];
    float c1 = cosb[s * HD + i];
    float s1 = sinb[s * HD + i];
    float c2 = cosb[s * HD + i + 32];
    float s2 = sinb[s * HD + i + 32];
    float y1 = x1 * c1 - x2 * s1;
    float y2 = x2 * c2 + x1 * s2;
    __nv_bfloat16 h1 = __float2bfloat16(y1);
    __nv_bfloat16 h2 = __float2bfloat16(y2);
    hi[base + i]      = h1;
    hi[base + i + 32] = h2;
    lo[base + i]      = __float2bfloat16(y1 - __bfloat162float(h1));
    lo[base + i + 32] = __float2bfloat16(y2 - __bfloat162float(h2));
}

// ---------------------------------------------------------------------------
// Flash attention on HMMA, split-bf16 (verified R9)
// ---------------------------------------------------------------------------
__global__ void __launch_bounds__(256, 1)
flash_attn_tc(const __nv_bfloat16* __restrict__ Qh, const __nv_bfloat16* __restrict__ Ql,
              const __nv_bfloat16* __restrict__ Kh, const __nv_bfloat16* __restrict__ Kl,
              const __nv_bfloat16* __restrict__ Vh, const __nv_bfloat16* __restrict__ Vl,
              __nv_bfloat16* __restrict__ Oh, __nv_bfloat16* __restrict__ Ol) {
    __shared__ __align__(16) char sm[32768];
    const int tid = threadIdx.x;
    const int wid = tid >> 5;
    const int lid = tid & 31;
    const int h = blockIdx.y;
    const int b = blockIdx.z;
    const int s0 = blockIdx.x * 128;
    const int kvh = h >> 2;
    const float scale = 0.125f;

    const uint32_t uS = smem_u32(sm);

    {
        const char* gqh = (const char*)(Qh + (((long)(b * SS + s0)) * NH + h) * HD);
        const char* gql = (const char*)(Ql + (((long)(b * SS + s0)) * NH + h) * HD);
        const long qstr = (long)NH * HD * 2;
#pragma unroll
        for (int i = 0; i < 4; i++) {
            int c = tid + i * 256;
            int row = c >> 3, ch = c & 7;
            uint32_t so = sw_off8(row, ch);
            *(uint4*)(sm + so)         = *(const uint4*)(gqh + (long)row * qstr + ch * 16);
            *(uint4*)(sm + 16384 + so) = *(const uint4*)(gql + (long)row * qstr + ch * 16);
        }
    }
    __syncthreads();

    uint32_t qhf[4][4], qlf[4][4];
    {
        const int arow = wid * 16 + (lid & 15);
#pragma unroll
        for (int ks = 0; ks < 4; ks++) {
            int ch = 2 * ks + (lid >> 4);
            uint32_t off = sw_off8(arow, ch);
            ldsm_x4(uS + off, qhf[ks][0], qhf[ks][1], qhf[ks][2], qhf[ks][3]);
            ldsm_x4(uS + 16384 + off, qlf[ks][0], qlf[ks][1], qlf[ks][2], qlf[ks][3]);
        }
    }
    __syncthreads();

    float o[8][4];
#pragma unroll
    for (int j = 0; j < 8; j++)
#pragma unroll
        for (int v = 0; v < 4; v++) o[j][v] = 0.f;
    float m0 = -INFINITY, m1 = -INFINITY, l0 = 0.f, l1 = 0.f;

    const char* gkh = (const char*)(Kh + (((long)(b * SS)) * NKV + kvh) * HD);
    const char* gkl = (const char*)(Kl + (((long)(b * SS)) * NKV + kvh) * HD);
    const char* gvh = (const char*)(Vh + (((long)(b * SS)) * NKV + kvh) * HD);
    const char* gvl = (const char*)(Vl + (((long)(b * SS)) * NKV + kvh) * HD);
    const long kvstr = (long)NKV * HD * 2;

    for (int j0 = 0; j0 < SS; j0 += 64) {
#pragma unroll
        for (int i = 0; i < 2; i++) {
            int c = tid + i * 256;
            int row = c >> 3, ch = c & 7;
            uint32_t so = sw_off8(row, ch);
            long go = (long)(j0 + row) * kvstr + ch * 16;
            *(uint4*)(sm + so)         = *(const uint4*)(gkh + go);
            *(uint4*)(sm + 8192 + so)  = *(const uint4*)(gkl + go);
            *(uint4*)(sm + 16384 + so) = *(const uint4*)(gvh + go);
            *(uint4*)(sm + 24576 + so) = *(const uint4*)(gvl + go);
        }
        __syncthreads();

        float sc[8][4];
#pragma unroll
        for (int j = 0; j < 8; j++)
#pragma unroll
            for (int v = 0; v < 4; v++) sc[j][v] = 0.f;

#pragma unroll
        for (int ks = 0; ks < 4; ks++) {
            uint32_t bh[8][2], bl[8][2];
            const int brow = lid & 15;
            const int bch = 2 * ks + (lid >> 4);
#pragma unroll
            for (int g = 0; g < 4; g++) {
                int r = g * 16 + brow;
                uint32_t off = sw_off8(r, bch);
                uint32_t t0, t1, t2, t3;
                ldsm_x4(uS + off, t0, t1, t2, t3);
                bh[2 * g][0] = t0; bh[2 * g][1] = t2;
                bh[2 * g + 1][0] = t1; bh[2 * g + 1][1] = t3;
                ldsm_x4(uS + 8192 + off, t0, t1, t2, t3);
                bl[2 * g][0] = t0; bl[2 * g][1] = t2;
                bl[2 * g + 1][0] = t1; bl[2 * g + 1][1] = t3;
            }
#pragma unroll
            for (int nj = 0; nj < 8; nj++) {
                mma_bf16(sc[nj], qhf[ks], bh[nj]);
                mma_bf16(sc[nj], qhf[ks], bl[nj]);
                mma_bf16(sc[nj], qlf[ks], bh[nj]);
            }
        }

        float mx0 = -INFINITY, mx1 = -INFINITY;
#pragma unroll
        for (int nj = 0; nj < 8; nj++) {
            sc[nj][0] *= scale; sc[nj][1] *= scale;
            sc[nj][2] *= scale; sc[nj][3] *= scale;
            mx0 = fmaxf(mx0, fmaxf(sc[nj][0], sc[nj][1]));
            mx1 = fmaxf(mx1, fmaxf(sc[nj][2], sc[nj][3]));
        }
        mx0 = fmaxf(mx0, __shfl_xor_sync(0xffffffffu, mx0, 1));
        mx0 = fmaxf(mx0, __shfl_xor_sync(0xffffffffu, mx0, 2));
        mx1 = fmaxf(mx1, __shfl_xor_sync(0xffffffffu, mx1, 1));
        mx1 = fmaxf(mx1, __shfl_xor_sync(0xffffffffu, mx1, 2));

        float mn0 = fmaxf(m0, mx0), mn1 = fmaxf(m1, mx1);
        float cor0 = __expf(m0 - mn0), cor1 = __expf(m1 - mn1);
        m0 = mn0; m1 = mn1;

        float sum0 = 0.f, sum1 = 0.f;
        uint32_t pah[4][4], pal[4][4];
#pragma unroll
        for (int nj = 0; nj < 8; nj++) {
            float p00 = __expf(sc[nj][0] - mn0);
            float p01 = __expf(sc[nj][1] - mn0);
            float p10 = __expf(sc[nj][2] - mn1);
            float p11 = __expf(sc[nj][3] - mn1);
            sum0 += p00 + p01;
            sum1 += p10 + p11;
            __nv_bfloat16 h00 = __float2bfloat16(p00), h01 = __float2bfloat16(p01);
            __nv_bfloat16 h10 = __float2bfloat16(p10), h11 = __float2bfloat16(p11);
            int ks = nj >> 1, half = nj & 1;
            pah[ks][half * 2]     = pack_bf16(__bfloat162float(h00), __bfloat162float(h01));
            pah[ks][half * 2 + 1] = pack_bf16(__bfloat162float(h10), __bfloat162float(h11));
            pal[ks][half * 2]     = pack_bf16(p00 - __bfloat162float(h00),
                                              p01 - __bfloat162float(h01));
            pal[ks][half * 2 + 1] = pack_bf16(p10 - __bfloat162float(h10),
                                              p11 - __bfloat162float(h11));
        }
        sum0 += __shfl_xor_sync(0xffffffffu, sum0, 1);
        sum0 += __shfl_xor_sync(0xffffffffu, sum0, 2);
        sum1 += __shfl_xor_sync(0xffffffffu, sum1, 1);
        sum1 += __shfl_xor_sync(0xffffffffu, sum1, 2);
        l0 = l0 * cor0 + sum0;
        l1 = l1 * cor1 + sum1;

#pragma unroll
        for (int nj = 0; nj < 8; nj++) {
            o[nj][0] *= cor0; o[nj][1] *= cor0;
            o[nj][2] *= cor1; o[nj][3] *= cor1;
        }

#pragma unroll
        for (int ks = 0; ks < 4; ks++) {
            uint32_t vh[8][2], vl[8][2];
            const int krow = ks * 16 + (lid & 15);
#pragma unroll
            for (int g = 0; g < 4; g++) {
                int ch = 2 * g + (lid >> 4);
                uint32_t off = sw_off8(krow, ch);
                uint32_t t0, t1, t2, t3;
                ldsm_x4_t(uS + 16384 + off, t0, t1, t2, t3);
                vh[2 * g][0] = t0; vh[2 * g][1] = t1;
                vh[2 * g + 1][0] = t2; vh[2 * g + 1][1] = t3;
                ldsm_x4_t(uS + 24576 + off, t0, t1, t2, t3);
                vl[2 * g][0] = t0; vl[2 * g][1] = t1;
                vl[2 * g + 1][0] = t2; vl[2 * g + 1][1] = t3;
            }
#pragma unroll
            for (int nj = 0; nj < 8; nj++) {
                mma_bf16(o[nj], pah[ks], vh[nj]);
                mma_bf16(o[nj], pah[ks], vl[nj]);
                mma_bf16(o[nj], pal[ks], vh[nj]);
            }
        }
        __syncthreads();
    }

    float inv0 = 1.f / l0, inv1 = 1.f / l1;
    int row0 = s0 + wid * 16 + (lid >> 2);
#pragma unroll
    for (int nj = 0; nj < 8; nj++) {
        int col = nj * 8 + (lid & 3) * 2;
        float v00 = o[nj][0] * inv0, v01 = o[nj][1] * inv0;
        float v10 = o[nj][2] * inv1, v11 = o[nj][3] * inv1;
        long a0 = (((long)(b * SS + row0)) * NH + h) * HD + col;
        long a1 = (((long)(b * SS + row0 + 8)) * NH + h) * HD + col;
        __nv_bfloat16 h00 = __float2bfloat16(v00), h01 = __float2bfloat16(v01);
        __nv_bfloat16 h10 = __float2bfloat16(v10), h11 = __float2bfloat16(v11);
        *(uint32_t*)(Oh + a0) = pack_bf16(__bfloat162float(h00), __bfloat162float(h01));
        *(uint32_t*)(Oh + a1) = pack_bf16(__bfloat162float(h10), __bfloat162float(h11));
        *(uint32_t*)(Ol + a0) = pack_bf16(v00 - __bfloat162float(h00),
                                          v01 - __bfloat162float(h01));
        *(uint32_t*)(Ol + a1) = pack_bf16(v10 - __bfloat162float(h10),
                                          v11 - __bfloat162float(h11));
    }
}

// ---------------------------------------------------------------------------
// Launch
// ---------------------------------------------------------------------------
#define GEMM_SMEM 65536

extern "C" void kernel_launch(void* const* d_in, const int* in_sizes, int n_in,
                              void* d_out, int out_size) {
    const float* x    = (const float*)d_in[0];
    const float* cosb = (const float*)d_in[1];
    const float* sinb = (const float*)d_in[2];
    const float* wq   = (const float*)d_in[3];
    const float* wk   = (const float*)d_in[4];
    const float* wv   = (const float*)d_in[5];
    const float* wo   = (const float*)d_in[6];
    float* out = (float*)d_out;

    // Idempotent, deterministic, capture-safe (no static guards per harness rules)
    cudaFuncSetAttribute(gemm_qkv, cudaFuncAttributeMaxDynamicSharedMemorySize, GEMM_SMEM);
    cudaFuncSetAttribute(gemm_tc, cudaFuncAttributeMaxDynamicSharedMemorySize, GEMM_SMEM);

    void *pq, *pk, *pv;
    cudaGetSymbolAddress(&pq, g_q);
    cudaGetSymbolAddress(&pk, g_k);
    cudaGetSymbolAddress(&pv, g_v);
    float* Q = (float*)pq;
    float* K = (float*)pk;
    float* V = (float*)pv;

    void *pxh, *pxl, *pqh2, *pql2, *pkh2, *pkl2, *pvh2, *pvl2, *poh, *pol, *pah, *pal;
    cudaGetSymbolAddress(&pxh, g_x_hi);  cudaGetSymbolAddress(&pxl, g_x_lo);
    cudaGetSymbolAddress(&pqh2, g_wq_hi); cudaGetSymbolAddress(&pql2, g_wq_lo);
    cudaGetSymbolAddress(&pkh2, g_wk_hi); cudaGetSymbolAddress(&pkl2, g_wk_lo);
    cudaGetSymbolAddress(&pvh2, g_wv_hi); cudaGetSymbolAddress(&pvl2, g_wv_lo);
    cudaGetSymbolAddress(&poh, g_wo_hi); cudaGetSymbolAddress(&pol, g_wo_lo);
    cudaGetSymbolAddress(&pah, g_a_hi);  cudaGetSymbolAddress(&pal, g_a_lo);

    void *qh, *ql, *kh, *kl, *vh, *vl;
    cudaGetSymbolAddress(&qh, g_qh); cudaGetSymbolAddress(&ql, g_ql);
    cudaGetSymbolAddress(&kh, g_kh); cudaGetSymbolAddress(&kl, g_kl);
    cudaGetSymbolAddress(&vh, g_vh); cudaGetSymbolAddress(&vl, g_vl);

    const int M = BB * SS;   // 4096
    const int HK = HIDD;     // 2048

    const int nx  = M * HIDD;
    const int nwq = NH * HD * HIDD;
    const int nwk = NKV * HD * HIDD;
    cvt_split<<<nx / 1024, 256>>>(x, (__nv_bfloat16*)pxh, (__nv_bfloat16*)pxl, nx);
    cvt_split<<<nwq / 1024, 256>>>(wq, (__nv_bfloat16*)pqh2, (__nv_bfloat16*)pql2, nwq);
    cvt_split<<<nwk / 1024, 256>>>(wk, (__nv_bfloat16*)pkh2, (__nv_bfloat16*)pkl2, nwk);
    cvt_split<<<nwk / 1024, 256>>>(wv, (__nv_bfloat16*)pvh2, (__nv_bfloat16*)pvl2, nwk);
    cvt_split<<<nwq / 1024, 256>>>(wo, (__nv_bfloat16*)poh, (__nv_bfloat16*)pol, nwq);

    // Fused Q/K/V projections
    gemm_qkv<<<dim3(24, M / 128), 256, GEMM_SMEM>>>(
        (const __nv_bfloat16*)pxh, (const __nv_bfloat16*)pxl,
        (const __nv_bfloat16*)pqh2, (const __nv_bfloat16*)pql2,
        (const __nv_bfloat16*)pkh2, (const __nv_bfloat16*)pkl2,
        (const __nv_bfloat16*)pvh2, (const __nv_bfloat16*)pvl2,
        Q, K, V);

    // RoPE + split (Q, K); plain split (V)
    int qpairs = BB * SS * NH * 32;
    int kpairs = BB * SS * NKV * 32;
    rope_split<<<(qpairs + 255) / 256, 256>>>(Q, cosb, sinb,
        (__nv_bfloat16*)qh, (__nv_bfloat16*)ql, NH, qpairs);
    rope_split<<<(kpairs + 255) / 256, 256>>>(K, cosb, sinb,
        (__nv_bfloat16*)kh, (__nv_bfloat16*)kl, NKV, kpairs);
    const int nv = BB * SS * NKV * HD;
    cvt_split<<<nv / 1024, 256>>>(V, (__nv_bfloat16*)vh, (__nv_bfloat16*)vl, nv);

    // Attention
    flash_attn_tc<<<dim3(SS / 128, NH, BB), 256>>>(
        (const __nv_bfloat16*)qh, (const __nv_bfloat16*)ql,
        (const __nv_bfloat16*)kh, (const __nv_bfloat16*)kl,
        (const __nv_bfloat16*)vh, (const __nv_bfloat16*)vl,
        (__nv_bfloat16*)pah, (__nv_bfloat16*)pal);

    // Output projection
    gemm_tc<<<dim3(HIDD / 128, M / 128), 256, GEMM_SMEM>>>(
        (const __nv_bfloat16*)pah, (const __nv_bfloat16*)pal,
        (const __nv_bfloat16*)poh, (const __nv_bfloat16*)pol, out, M, HIDD, HK);
}

// round 15
// speedup vs baseline: 3.7205x; 1.1779x over previous
#include <cuda_runtime.h>
#include <cuda_bf16.h>
#include <math.h>
#include <stdint.h>

// Problem constants
#define BB   2
#define SS   2048
#define HIDD 2048
#define NH   32
#define NKV  8
#define HD   64
#define NREP 4

// ---------------------------------------------------------------------------
// Device-global scratch (allocation-free rule)
// ---------------------------------------------------------------------------
__device__ float g_q[BB * SS * NH * HD];     // fp32 pre-RoPE
__device__ float g_k[BB * SS * NKV * HD];
__device__ float g_v[BB * SS * NKV * HD];

__device__ __nv_bfloat16 g_x_hi[BB * SS * HIDD];
__device__ __nv_bfloat16 g_x_lo[BB * SS * HIDD];
__device__ __nv_bfloat16 g_wq_hi[NH * HD * HIDD];
__device__ __nv_bfloat16 g_wq_lo[NH * HD * HIDD];
__device__ __nv_bfloat16 g_wk_hi[NKV * HD * HIDD];
__device__ __nv_bfloat16 g_wk_lo[NKV * HD * HIDD];
__device__ __nv_bfloat16 g_wv_hi[NKV * HD * HIDD];
__device__ __nv_bfloat16 g_wv_lo[NKV * HD * HIDD];
__device__ __nv_bfloat16 g_wo_hi[HIDD * NH * HD];
__device__ __nv_bfloat16 g_wo_lo[HIDD * NH * HD];
__device__ __nv_bfloat16 g_a_hi[BB * SS * NH * HD];
__device__ __nv_bfloat16 g_a_lo[BB * SS * NH * HD];

__device__ __nv_bfloat16 g_qh[BB * SS * NH * HD];
__device__ __nv_bfloat16 g_ql[BB * SS * NH * HD];
__device__ __nv_bfloat16 g_kh[BB * SS * NKV * HD];
__device__ __nv_bfloat16 g_kl[BB * SS * NKV * HD];
__device__ __nv_bfloat16 g_vh[BB * SS * NKV * HD];
__device__ __nv_bfloat16 g_vl[BB * SS * NKV * HD];

// ---------------------------------------------------------------------------
// Helpers
// ---------------------------------------------------------------------------
__device__ __forceinline__ uint32_t smem_u32(const void* p) {
    uint32_t a;
    asm("{ .reg .u64 t; cvta.to.shared.u64 t, %1; cvt.u32.u64 %0, t; }"
        : "=r"(a) : "l"(p));
    return a;
}

// Tiles with 128B rows, 8 x 16B chunks: conflict-free for STS.128/cp.async,
// ldmatrix and ldmatrix.trans (proven in R9 flash kernel).
__device__ __forceinline__ uint32_t sw_off8(int row, int ch) {
    return (uint32_t)(row * 128 + ((ch ^ (row & 7)) << 4));
}

__device__ __forceinline__ void ldsm_x4(uint32_t addr, uint32_t& r0, uint32_t& r1,
                                        uint32_t& r2, uint32_t& r3) {
    asm volatile("ldmatrix.sync.aligned.m8n8.x4.shared.b16 {%0,%1,%2,%3}, [%4];"
                 : "=r"(r0), "=r"(r1), "=r"(r2), "=r"(r3) : "r"(addr));
}
__device__ __forceinline__ void ldsm_x4_t(uint32_t addr, uint32_t& r0, uint32_t& r1,
                                          uint32_t& r2, uint32_t& r3) {
    asm volatile("ldmatrix.sync.aligned.m8n8.x4.trans.shared.b16 {%0,%1,%2,%3}, [%4];"
                 : "=r"(r0), "=r"(r1), "=r"(r2), "=r"(r3) : "r"(addr));
}

__device__ __forceinline__ void mma_bf16(float* c, const uint32_t* a, const uint32_t* b) {
    asm volatile(
        "mma.sync.aligned.m16n8k16.row.col.f32.bf16.bf16.f32 "
        "{%0,%1,%2,%3}, {%4,%5,%6,%7}, {%8,%9}, {%0,%1,%2,%3};"
        : "+f"(c[0]), "+f"(c[1]), "+f"(c[2]), "+f"(c[3])
        : "r"(a[0]), "r"(a[1]), "r"(a[2]), "r"(a[3]), "r"(b[0]), "r"(b[1]));
}

__device__ __forceinline__ uint32_t pack_bf16(float a, float b) {
    __nv_bfloat162 t = __floats2bfloat162_rn(a, b);
    return *(uint32_t*)&t;
}

__device__ __forceinline__ void cp_async16(uint32_t saddr, const void* g) {
    asm volatile("cp.async.cg.shared.global [%0], [%1], 16;" :: "r"(saddr), "l"(g));
}
#define CP_COMMIT() asm volatile("cp.async.commit_group;")
#define CP_WAIT(n)  asm volatile("cp.async.wait_group %0;" :: "n"(n))

// ---------------------------------------------------------------------------
// Split fp32 -> (hi, lo) bf16
// ---------------------------------------------------------------------------
__global__ void cvt_split(const float* __restrict__ in,
                          __nv_bfloat16* __restrict__ hi,
                          __nv_bfloat16* __restrict__ lo, int n) {
    int i = (blockIdx.x * blockDim.x + threadIdx.x) * 4;
    if (i >= n) return;
    float4 f = *(const float4*)(in + i);
    __nv_bfloat16 h0 = __float2bfloat16(f.x);
    __nv_bfloat16 h1 = __float2bfloat16(f.y);
    __nv_bfloat16 h2 = __float2bfloat16(f.z);
    __nv_bfloat16 h3 = __float2bfloat16(f.w);
    __nv_bfloat16 l0 = __float2bfloat16(f.x - __bfloat162float(h0));
    __nv_bfloat16 l1 = __float2bfloat16(f.y - __bfloat162float(h1));
    __nv_bfloat16 l2 = __float2bfloat16(f.z - __bfloat162float(h2));
    __nv_bfloat16 l3 = __float2bfloat16(f.w - __bfloat162float(h3));
    __nv_bfloat162* hp = (__nv_bfloat162*)(hi + i);
    __nv_bfloat162* lp = (__nv_bfloat162*)(lo + i);
    hp[0] = __nv_bfloat162(h0, h1);
    hp[1] = __nv_bfloat162(h2, h3);
    lp[0] = __nv_bfloat162(l0, l1);
    lp[1] = __nv_bfloat162(l2, l3);
}

// ---------------------------------------------------------------------------
// Pipelined split-bf16 GEMM body, BK=64 (32 iters for K=2048).
// Stage (64KB): Ah@0 Al@16384 Bh@32768 Bl@49152; 2 stages (128KB dynamic).
// MMA phases reordered: all hi*hi, all hi*lo, all lo*hi (16-wide ILP each).
// ---------------------------------------------------------------------------
__device__ __forceinline__ void gemm_body(
    const char* __restrict__ aH, const char* __restrict__ aL,
    const char* __restrict__ bH, const char* __restrict__ bL,
    float* __restrict__ C, int ldc, int K, char* sm) {
    const int tid = threadIdx.x;
    const int wid = tid >> 5;
    const int lid = tid & 31;
    const int m0w = (wid >> 1) * 32;
    const int n0w = (wid & 1) * 64;
    const long ldb = (long)K * 2;

    // 4 x 16B chunks per thread per array (128 rows x 128B tile)
    uint32_t so[4];
    long go[4];
#pragma unroll
    for (int i = 0; i < 4; i++) {
        int c = tid + i * 256;
        int row = c >> 3, ch = c & 7;
        so[i] = sw_off8(row, ch);
        go[i] = (long)row * ldb + ch * 16;
    }

    const uint32_t uS = smem_u32(sm);

    float acc[2][8][4];
#pragma unroll
    for (int i = 0; i < 2; i++)
#pragma unroll
        for (int j = 0; j < 8; j++)
#pragma unroll
            for (int v = 0; v < 4; v++) acc[i][j][v] = 0.f;

    const int niter = K >> 6;

    // issue stage 0
#pragma unroll
    for (int i = 0; i < 4; i++) {
        cp_async16(uS + so[i], aH + go[i]);
        cp_async16(uS + 16384 + so[i], aL + go[i]);
        cp_async16(uS + 32768 + so[i], bH + go[i]);
        cp_async16(uS + 49152 + so[i], bL + go[i]);
    }
    CP_COMMIT();

    for (int it = 0; it < niter; it++) {
        if (it + 1 < niter) {
            const uint32_t sb = uS + ((it + 1) & 1) * 65536;
            const long kb = (long)(it + 1) * 128;
#pragma unroll
            for (int i = 0; i < 4; i++) {
                cp_async16(sb + so[i], aH + go[i] + kb);
                cp_async16(sb + 16384 + so[i], aL + go[i] + kb);
                cp_async16(sb + 32768 + so[i], bH + go[i] + kb);
                cp_async16(sb + 49152 + so[i], bL + go[i] + kb);
            }
            CP_COMMIT();
            CP_WAIT(1);
        } else {
            CP_WAIT(0);
        }
        __syncthreads();

        const uint32_t uAh = uS + (it & 1) * 65536;
        const uint32_t uAl = uAh + 16384;
        const uint32_t uBh = uAh + 32768;
        const uint32_t uBl = uAh + 49152;

#pragma unroll
        for (int ks = 0; ks < 4; ks++) {
            uint32_t ah[2][4], al[2][4], bh[8][2], bl[8][2];
            const int arow = m0w + (lid & 15);
            const int ach = ks * 2 + (lid >> 4);
#pragma unroll
            for (int mi = 0; mi < 2; mi++) {
                uint32_t off = sw_off8(arow + mi * 16, ach);
                ldsm_x4(uAh + off, ah[mi][0], ah[mi][1], ah[mi][2], ah[mi][3]);
                ldsm_x4(uAl + off, al[mi][0], al[mi][1], al[mi][2], al[mi][3]);
            }
            const int brow = n0w + (lid & 15);
#pragma unroll
            for (int g = 0; g < 4; g++) {
                uint32_t off = sw_off8(brow + g * 16, ach);
                uint32_t t0, t1, t2, t3;
                ldsm_x4(uBh + off, t0, t1, t2, t3);
                bh[2 * g][0] = t0; bh[2 * g][1] = t2;
                bh[2 * g + 1][0] = t1; bh[2 * g + 1][1] = t3;
                ldsm_x4(uBl + off, t0, t1, t2, t3);
                bl[2 * g][0] = t0; bl[2 * g][1] = t2;
                bl[2 * g + 1][0] = t1; bl[2 * g + 1][1] = t3;
            }
            // Phase 1: hi*hi (16 independent accumulators)
#pragma unroll
            for (int mi = 0; mi < 2; mi++)
#pragma unroll
                for (int nj = 0; nj < 8; nj++)
                    mma_bf16(acc[mi][nj], ah[mi], bh[nj]);
            // Phase 2: hi*lo
#pragma unroll
            for (int mi = 0; mi < 2; mi++)
#pragma unroll
                for (int nj = 0; nj < 8; nj++)
                    mma_bf16(acc[mi][nj], ah[mi], bl[nj]);
            // Phase 3: lo*hi
#pragma unroll
            for (int mi = 0; mi < 2; mi++)
#pragma unroll
                for (int nj = 0; nj < 8; nj++)
                    mma_bf16(acc[mi][nj], al[mi], bh[nj]);
        }
        __syncthreads();
    }

#pragma unroll
    for (int mi = 0; mi < 2; mi++) {
#pragma unroll
        for (int nj = 0; nj < 8; nj++) {
            int row = m0w + mi * 16 + (lid >> 2);
            int col = n0w + nj * 8 + (lid & 3) * 2;
            *(float2*)&C[(long)row * ldc + col] = make_float2(acc[mi][nj][0], acc[mi][nj][1]);
            *(float2*)&C[(long)(row + 8) * ldc + col] = make_float2(acc[mi][nj][2], acc[mi][nj][3]);
        }
    }
}

// ---------------------------------------------------------------------------
// Fused Q/K/V projection GEMM. grid = (24, M/128).
// ---------------------------------------------------------------------------
__global__ void __launch_bounds__(256, 1)
gemm_qkv(const __nv_bfloat16* __restrict__ Xh, const __nv_bfloat16* __restrict__ Xl,
         const __nv_bfloat16* __restrict__ Wqh, const __nv_bfloat16* __restrict__ Wql,
         const __nv_bfloat16* __restrict__ Wkh, const __nv_bfloat16* __restrict__ Wkl,
         const __nv_bfloat16* __restrict__ Wvh, const __nv_bfloat16* __restrict__ Wvl,
         float* __restrict__ Q, float* __restrict__ K, float* __restrict__ V) {
    extern __shared__ __align__(16) char sm[];
    const int bx = blockIdx.x;
    const int m0 = blockIdx.y * 128;
    const int KK = HIDD;

    const __nv_bfloat16 *bh, *bl;
    float* C;
    int ldc, n0;
    if (bx < 16)      { bh = Wqh; bl = Wql; C = Q; ldc = NH * HD;  n0 = bx * 128; }
    else if (bx < 20) { bh = Wkh; bl = Wkl; C = K; ldc = NKV * HD; n0 = (bx - 16) * 128; }
    else              { bh = Wvh; bl = Wvl; C = V; ldc = NKV * HD; n0 = (bx - 20) * 128; }

    gemm_body((const char*)(Xh + (long)m0 * KK), (const char*)(Xl + (long)m0 * KK),
              (const char*)(bh + (long)n0 * KK), (const char*)(bl + (long)n0 * KK),
              C + (long)m0 * ldc + n0, ldc, KK, sm);
}

// ---------------------------------------------------------------------------
// Generic NT GEMM (output projection). grid = (N/128, M/128).
// ---------------------------------------------------------------------------
__global__ void __launch_bounds__(256, 1)
gemm_tc(const __nv_bfloat16* __restrict__ Ahi, const __nv_bfloat16* __restrict__ Alo,
        const __nv_bfloat16* __restrict__ Bhi, const __nv_bfloat16* __restrict__ Blo,
        float* __restrict__ C, int M, int N, int K) {
    extern __shared__ __align__(16) char sm[];
    const int m0 = blockIdx.y * 128;
    const int n0 = blockIdx.x * 128;
    gemm_body((const char*)(Ahi + (long)m0 * K), (const char*)(Alo + (long)m0 * K),
              (const char*)(Bhi + (long)n0 * K), (const char*)(Blo + (long)n0 * K),
              C + (long)m0 * N + n0, N, K, sm);
}

// ---------------------------------------------------------------------------
// RoPE + split
// ---------------------------------------------------------------------------
__global__ void rope_split(const float* __restrict__ x,
                           const float* __restrict__ cosb,
                           const float* __restrict__ sinb,
                           __nv_bfloat16* __restrict__ hi,
                           __nv_bfloat16* __restrict__ lo,
                           int nheads, int total_pairs) {
    int idx = blockIdx.x * blockDim.x + threadIdx.x;
    if (idx >= total_pairs) return;
    int i = idx & 31;
    int h = (idx >> 5) % nheads;
    int s = (idx / (32 * nheads)) % SS;
    int b = idx / (32 * nheads * SS);
    long base = ((long)(b * SS + s) * nheads + h) * HD;
    float x1 = x[base + i];
    float x2 = x[base + i + 32];
    float c1 = cosb[s * HD + i];
    float s1 = sinb[s * HD + i];
    float c2 = cosb[s * HD + i + 32];
    float s2 = sinb[s * HD + i + 32];
    float y1 = x1 * c1 - x2 * s1;
    float y2 = x2 * c2 + x1 * s2;
    __nv_bfloat16 h1 = __float2bfloat16(y1);
    __nv_bfloat16 h2 = __float2bfloat16(y2);
    hi[base + i]      = h1;
    hi[base + i + 32] = h2;
    lo[base + i]      = __float2bfloat16(y1 - __bfloat162float(h1));
    lo[base + i + 32] = __float2bfloat16(y2 - __bfloat162float(h2));
}

// ---------------------------------------------------------------------------
// Flash attention on HMMA, split-bf16, cp.async double-buffered K/V.
// Dynamic SMEM 64KB: stage s at s*32768: Kh@0 Kl@8192 Vh@16384 Vl@24576.
// Q staged in [0,32768) before the KV pipeline starts (then overwritten).
// ---------------------------------------------------------------------------
__global__ void __launch_bounds__(256, 1)
flash_attn_tc(const __nv_bfloat16* __restrict__ Qh, const __nv_bfloat16* __restrict__ Ql,
              const __nv_bfloat16* __restrict__ Kh, const __nv_bfloat16* __restrict__ Kl,
              const __nv_bfloat16* __restrict__ Vh, const __nv_bfloat16* __restrict__ Vl,
              __nv_bfloat16* __restrict__ Oh, __nv_bfloat16* __restrict__ Ol) {
    extern __shared__ __align__(16) char sm[];
    const int tid = threadIdx.x;
    const int wid = tid >> 5;
    const int lid = tid & 31;
    const int h = blockIdx.y;
    const int b = blockIdx.z;
    const int s0 = blockIdx.x * 128;
    const int kvh = h >> 2;
    const float scale = 0.125f;

    const uint32_t uS = smem_u32(sm);

    // ---- stage Q (hi@0, lo@16384), extract fragments
    {
        const char* gqh = (const char*)(Qh + (((long)(b * SS + s0)) * NH + h) * HD);
        const char* gql = (const char*)(Ql + (((long)(b * SS + s0)) * NH + h) * HD);
        const long qstr = (long)NH * HD * 2;
#pragma unroll
        for (int i = 0; i < 4; i++) {
            int c = tid + i * 256;
            int row = c >> 3, ch = c & 7;
            uint32_t so = sw_off8(row, ch);
            *(uint4*)(sm + so)         = *(const uint4*)(gqh + (long)row * qstr + ch * 16);
            *(uint4*)(sm + 16384 + so) = *(const uint4*)(gql + (long)row * qstr + ch * 16);
        }
    }
    __syncthreads();

    uint32_t qhf[4][4], qlf[4][4];
    {
        const int arow = wid * 16 + (lid & 15);
#pragma unroll
        for (int ks = 0; ks < 4; ks++) {
            int ch = 2 * ks + (lid >> 4);
            uint32_t off = sw_off8(arow, ch);
            ldsm_x4(uS + off, qhf[ks][0], qhf[ks][1], qhf[ks][2], qhf[ks][3]);
            ldsm_x4(uS + 16384 + off, qlf[ks][0], qlf[ks][1], qlf[ks][2], qlf[ks][3]);
        }
    }
    __syncthreads();   // Q region free for KV stage 0

    float o[8][4];
#pragma unroll
    for (int j = 0; j < 8; j++)
#pragma unroll
        for (int v = 0; v < 4; v++) o[j][v] = 0.f;
    float m0 = -INFINITY, m1 = -INFINITY, l0 = 0.f, l1 = 0.f;

    const char* gkh = (const char*)(Kh + (((long)(b * SS)) * NKV + kvh) * HD);
    const char* gkl = (const char*)(Kl + (((long)(b * SS)) * NKV + kvh) * HD);
    const char* gvh = (const char*)(Vh + (((long)(b * SS)) * NKV + kvh) * HD);
    const char* gvl = (const char*)(Vl + (((long)(b * SS)) * NKV + kvh) * HD);
    const long kvstr = (long)NKV * HD * 2;

    // per-thread KV chunk slots (2 per array)
    uint32_t kso[2];
    long kgo_row[2];
    int kch[2];
#pragma unroll
    for (int i = 0; i < 2; i++) {
        int c = tid + i * 256;
        int row = c >> 3, ch = c & 7;
        kso[i] = sw_off8(row, ch);
        kgo_row[i] = row;
        kch[i] = ch;
    }

    // issue KV stage 0
#pragma unroll
    for (int i = 0; i < 2; i++) {
        long go = kgo_row[i] * kvstr + kch[i] * 16;
        cp_async16(uS + kso[i], gkh + go);
        cp_async16(uS + 8192 + kso[i], gkl + go);
        cp_async16(uS + 16384 + kso[i], gvh + go);
        cp_async16(uS + 24576 + kso[i], gvl + go);
    }
    CP_COMMIT();

    const int ntiles = SS / 64;   // 32
    for (int t = 0; t < ntiles; t++) {
        if (t + 1 < ntiles) {
            const uint32_t sb = uS + ((t + 1) & 1) * 32768;
            const long j1 = (long)(t + 1) * 64;
#pragma unroll
            for (int i = 0; i < 2; i++) {
                long go = (j1 + kgo_row[i]) * kvstr + kch[i] * 16;
                cp_async16(sb + kso[i], gkh + go);
                cp_async16(sb + 8192 + kso[i], gkl + go);
                cp_async16(sb + 16384 + kso[i], gvh + go);
                cp_async16(sb + 24576 + kso[i], gvl + go);
            }
            CP_COMMIT();
            CP_WAIT(1);
        } else {
            CP_WAIT(0);
        }
        __syncthreads();

        const uint32_t sB = uS + (t & 1) * 32768;

        float sc[8][4];
#pragma unroll
        for (int j = 0; j < 8; j++)
#pragma unroll
            for (int v = 0; v < 4; v++) sc[j][v] = 0.f;

#pragma unroll
        for (int ks = 0; ks < 4; ks++) {
            uint32_t bh[8][2], bl[8][2];
            const int brow = lid & 15;
            const int bch = 2 * ks + (lid >> 4);
#pragma unroll
            for (int g = 0; g < 4; g++) {
                int r = g * 16 + brow;
                uint32_t off = sw_off8(r, bch);
                uint32_t t0, t1, t2, t3;
                ldsm_x4(sB + off, t0, t1, t2, t3);
                bh[2 * g][0] = t0; bh[2 * g][1] = t2;
                bh[2 * g + 1][0] = t1; bh[2 * g + 1][1] = t3;
                ldsm_x4(sB + 8192 + off, t0, t1, t2, t3);
                bl[2 * g][0] = t0; bl[2 * g][1] = t2;
                bl[2 * g + 1][0] = t1; bl[2 * g + 1][1] = t3;
            }
#pragma unroll
            for (int nj = 0; nj < 8; nj++)
                mma_bf16(sc[nj], qhf[ks], bh[nj]);
#pragma unroll
            for (int nj = 0; nj < 8; nj++)
                mma_bf16(sc[nj], qhf[ks], bl[nj]);
#pragma unroll
            for (int nj = 0; nj < 8; nj++)
                mma_bf16(sc[nj], qlf[ks], bh[nj]);
        }

        float mx0 = -INFINITY, mx1 = -INFINITY;
#pragma unroll
        for (int nj = 0; nj < 8; nj++) {
            sc[nj][0] *= scale; sc[nj][1] *= scale;
            sc[nj][2] *= scale; sc[nj][3] *= scale;
            mx0 = fmaxf(mx0, fmaxf(sc[nj][0], sc[nj][1]));
            mx1 = fmaxf(mx1, fmaxf(sc[nj][2], sc[nj][3]));
        }
        mx0 = fmaxf(mx0, __shfl_xor_sync(0xffffffffu, mx0, 1));
        mx0 = fmaxf(mx0, __shfl_xor_sync(0xffffffffu, mx0, 2));
        mx1 = fmaxf(mx1, __shfl_xor_sync(0xffffffffu, mx1, 1));
        mx1 = fmaxf(mx1, __shfl_xor_sync(0xffffffffu, mx1, 2));

        float mn0 = fmaxf(m0, mx0), mn1 = fmaxf(m1, mx1);
        float cor0 = __expf(m0 - mn0), cor1 = __expf(m1 - mn1);
        m0 = mn0; m1 = mn1;

        float sum0 = 0.f, sum1 = 0.f;
        uint32_t pah[4][4], pal[4][4];
#pragma unroll
        for (int nj = 0; nj < 8; nj++) {
            float p00 = __expf(sc[nj][0] - mn0);
            float p01 = __expf(sc[nj][1] - mn0);
            float p10 = __expf(sc[nj][2] - mn1);
            float p11 = __expf(sc[nj][3] - mn1);
            sum0 += p00 + p01;
            sum1 += p10 + p11;
            __nv_bfloat16 h00 = __float2bfloat16(p00), h01 = __float2bfloat16(p01);
            __nv_bfloat16 h10 = __float2bfloat16(p10), h11 = __float2bfloat16(p11);
            int ks = nj >> 1, half = nj & 1;
            pah[ks][half * 2]     = pack_bf16(__bfloat162float(h00), __bfloat162float(h01));
            pah[ks][half * 2 + 1] = pack_bf16(__bfloat162float(h10), __bfloat162float(h11));
            pal[ks][half * 2]     = pack_bf16(p00 - __bfloat162float(h00),
                                              p01 - __bfloat162float(h01));
            pal[ks][half * 2 + 1] = pack_bf16(p10 - __bfloat162float(h10),
                                              p11 - __bfloat162float(h11));
        }
        sum0 += __shfl_xor_sync(0xffffffffu, sum0, 1);
        sum0 += __shfl_xor_sync(0xffffffffu, sum0, 2);
        sum1 += __shfl_xor_sync(0xffffffffu, sum1, 1);
        sum1 += __shfl_xor_sync(0xffffffffu, sum1, 2);
        l0 = l0 * cor0 + sum0;
        l1 = l1 * cor1 + sum1;

#pragma unroll
        for (int nj = 0; nj < 8; nj++) {
            o[nj][0] *= cor0; o[nj][1] *= cor0;
            o[nj][2] *= cor1; o[nj][3] *= cor1;
        }

#pragma unroll
        for (int ks = 0; ks < 4; ks++) {
            uint32_t vh[8][2], vl[8][2];
            const int krow = ks * 16 + (lid & 15);
#pragma unroll
            for (int g = 0; g < 4; g++) {
                int ch = 2 * g + (lid >> 4);
                uint32_t off = sw_off8(krow, ch);
                uint32_t t0, t1, t2, t3;
                ldsm_x4_t(sB + 16384 + off, t0, t1, t2, t3);
                vh[2 * g][0] = t0; vh[2 * g][1] = t1;
                vh[2 * g + 1][0] = t2; vh[2 * g + 1][1] = t3;
                ldsm_x4_t(sB + 24576 + off, t0, t1, t2, t3);
                vl[2 * g][0] = t0; vl[2 * g][1] = t1;
                vl[2 * g + 1][0] = t2; vl[2 * g + 1][1] = t3;
            }
#pragma unroll
            for (int nj = 0; nj < 8; nj++)
                mma_bf16(o[nj], pah[ks], vh[nj]);
#pragma unroll
            for (int nj = 0; nj < 8; nj++)
                mma_bf16(o[nj], pah[ks], vl[nj]);
#pragma unroll
            for (int nj = 0; nj < 8; nj++)
                mma_bf16(o[nj], pal[ks], vh[nj]);
        }
        __syncthreads();   // protect buffer (t&1) before re-issue at t+1
    }

    float inv0 = 1.f / l0, inv1 = 1.f / l1;
    int row0 = s0 + wid * 16 + (lid >> 2);
#pragma unroll
    for (int nj = 0; nj < 8; nj++) {
        int col = nj * 8 + (lid & 3) * 2;
        float v00 = o[nj][0] * inv0, v01 = o[nj][1] * inv0;
        float v10 = o[nj][2] * inv1, v11 = o[nj][3] * inv1;
        long a0 = (((long)(b * SS + row0)) * NH + h) * HD + col;
        long a1 = (((long)(b * SS + row0 + 8)) * NH + h) * HD + col;
        __nv_bfloat16 h00 = __float2bfloat16(v00), h01 = __float2bfloat16(v01);
        __nv_bfloat16 h10 = __float2bfloat16(v10), h11 = __float2bfloat16(v11);
        *(uint32_t*)(Oh + a0) = pack_bf16(__bfloat162float(h00), __bfloat162float(h01));
        *(uint32_t*)(Oh + a1) = pack_bf16(__bfloat162float(h10), __bfloat162float(h11));
        *(uint32_t*)(Ol + a0) = pack_bf16(v00 - __bfloat162float(h00),
                                          v01 - __bfloat162float(h01));
        *(uint32_t*)(Ol + a1) = pack_bf16(v10 - __bfloat162float(h10),
                                          v11 - __bfloat162float(h11));
    }
}

// ---------------------------------------------------------------------------
// Launch
// ---------------------------------------------------------------------------
#define GEMM_SMEM 131072
#define ATT_SMEM  65536

extern "C" void kernel_launch(void* const* d_in, const int* in_sizes, int n_in,
                              void* d_out, int out_size) {
    const float* x    = (const float*)d_in[0];
    const float* cosb = (const float*)d_in[1];
    const float* sinb = (const float*)d_in[2];
    const float* wq   = (const float*)d_in[3];
    const float* wk   = (const float*)d_in[4];
    const float* wv   = (const float*)d_in[5];
    const float* wo   = (const float*)d_in[6];
    float* out = (float*)d_out;

    // Idempotent, deterministic, capture-safe
    cudaFuncSetAttribute(gemm_qkv, cudaFuncAttributeMaxDynamicSharedMemorySize, GEMM_SMEM);
    cudaFuncSetAttribute(gemm_tc, cudaFuncAttributeMaxDynamicSharedMemorySize, GEMM_SMEM);
    cudaFuncSetAttribute(flash_attn_tc, cudaFuncAttributeMaxDynamicSharedMemorySize, ATT_SMEM);

    void *pq, *pk, *pv;
    cudaGetSymbolAddress(&pq, g_q);
    cudaGetSymbolAddress(&pk, g_k);
    cudaGetSymbolAddress(&pv, g_v);
    float* Q = (float*)pq;
    float* K = (float*)pk;
    float* V = (float*)pv;

    void *pxh, *pxl, *pqh2, *pql2, *pkh2, *pkl2, *pvh2, *pvl2, *poh, *pol, *pah, *pal;
    cudaGetSymbolAddress(&pxh, g_x_hi);  cudaGetSymbolAddress(&pxl, g_x_lo);
    cudaGetSymbolAddress(&pqh2, g_wq_hi); cudaGetSymbolAddress(&pql2, g_wq_lo);
    cudaGetSymbolAddress(&pkh2, g_wk_hi); cudaGetSymbolAddress(&pkl2, g_wk_lo);
    cudaGetSymbolAddress(&pvh2, g_wv_hi); cudaGetSymbolAddress(&pvl2, g_wv_lo);
    cudaGetSymbolAddress(&poh, g_wo_hi); cudaGetSymbolAddress(&pol, g_wo_lo);
    cudaGetSymbolAddress(&pah, g_a_hi);  cudaGetSymbolAddress(&pal, g_a_lo);

    void *qh, *ql, *kh, *kl, *vh, *vl;
    cudaGetSymbolAddress(&qh, g_qh); cudaGetSymbolAddress(&ql, g_ql);
    cudaGetSymbolAddress(&kh, g_kh); cudaGetSymbolAddress(&kl, g_kl);
    cudaGetSymbolAddress(&vh, g_vh); cudaGetSymbolAddress(&vl, g_vl);

    const int M = BB * SS;   // 4096
    const int HK = HIDD;     // 2048

    const int nx  = M * HIDD;
    const int nwq = NH * HD * HIDD;
    const int nwk = NKV * HD * HIDD;
    cvt_split<<<nx / 1024, 256>>>(x, (__nv_bfloat16*)pxh, (__nv_bfloat16*)pxl, nx);
    cvt_split<<<nwq / 1024, 256>>>(wq, (__nv_bfloat16*)pqh2, (__nv_bfloat16*)pql2, nwq);
    cvt_split<<<nwk / 1024, 256>>>(wk, (__nv_bfloat16*)pkh2, (__nv_bfloat16*)pkl2, nwk);
    cvt_split<<<nwk / 1024, 256>>>(wv, (__nv_bfloat16*)pvh2, (__nv_bfloat16*)pvl2, nwk);
    cvt_split<<<nwq / 1024, 256>>>(wo, (__nv_bfloat16*)poh, (__nv_bfloat16*)pol, nwq);

    // Fused Q/K/V projections
    gemm_qkv<<<dim3(24, M / 128), 256, GEMM_SMEM>>>(
        (const __nv_bfloat16*)pxh, (const __nv_bfloat16*)pxl,
        (const __nv_bfloat16*)pqh2, (const __nv_bfloat16*)pql2,
        (const __nv_bfloat16*)pkh2, (const __nv_bfloat16*)pkl2,
        (const __nv_bfloat16*)pvh2, (const __nv_bfloat16*)pvl2,
        Q, K, V);

    // RoPE + split (Q, K); plain split (V)
    int qpairs = BB * SS * NH * 32;
    int kpairs = BB * SS * NKV * 32;
    rope_split<<<(qpairs + 255) / 256, 256>>>(Q, cosb, sinb,
        (__nv_bfloat16*)qh, (__nv_bfloat16*)ql, NH, qpairs);
    rope_split<<<(kpairs + 255) / 256, 256>>>(K, cosb, sinb,
        (__nv_bfloat16*)kh, (__nv_bfloat16*)kl, NKV, kpairs);
    const int nv = BB * SS * NKV * HD;
    cvt_split<<<nv / 1024, 256>>>(V, (__nv_bfloat16*)vh, (__nv_bfloat16*)vl, nv);

    // Attention
    flash_attn_tc<<<dim3(SS / 128, NH, BB), 256, ATT_SMEM>>>(
        (const __nv_bfloat16*)qh, (const __nv_bfloat16*)ql,
        (const __nv_bfloat16*)kh, (const __nv_bfloat16*)kl,
        (const __nv_bfloat16*)vh, (const __nv_bfloat16*)vl,
        (__nv_bfloat16*)pah, (__nv_bfloat16*)pal);

    // Output projection
    gemm_tc<<<dim3(HIDD / 128, M / 128), 256, GEMM_SMEM>>>(
        (const __nv_bfloat16*)pah, (const __nv_bfloat16*)pal,
        (const __nv_bfloat16*)poh, (const __nv_bfloat16*)pol, out, M, HIDD, HK);
}